// round 4
// baseline (speedup 1.0000x reference)
#include <cuda_runtime.h>
#include <cuda_bf16.h>
#include <cstdint>

// ---------------- problem constants ----------------
#define H     8
#define Bn    32768
#define INF   16
#define CI    32
#define OF    32
#define KREAL 561          // 33 channels * 17 inputs (33*17 == 561 exactly)
#define KPAD  576          // 36 k-steps of 16
#define NKSTEP 36
#define MTILE 128          // samples per CTA
#define CHUNK_K 192        // K per staged chunk
#define NCHUNK 3
#define KSC   12           // ksteps per chunk

// fragment-linear W in device-global scratch:
// u32 index = (((h*2 + s)*NKSTEP + ks)*4 + nt)*32*2 + lane*2 + j   (j: b0/b1)
#define WF_U32_PER_HEAD (2 * NKSTEP * 4 * 32 * 2)   // 18432
__device__ uint32_t g_wf[H * WF_U32_PER_HEAD];

// ---------------- smem layout (bytes) ----------------
#define SM_WF   0
#define WF_BYTES (WF_U32_PER_HEAD * 4)              // 73728
#define PROW    400                                  // 192 bf16 = 384B + 16B pad (16B-mult, stride%32banks=4)
#define SM_PH   (SM_WF + WF_BYTES)                   // 73728
#define SM_PL   (SM_PH + MTILE * PROW)               // 124928
#define SM_XS   (SM_PL + MTILE * PROW)               // 176128
#define XSTR    129                                  // float stride (odd -> conflict-free transpose fill)
#define SM_CS   (SM_XS + 17 * XSTR * 4 + 12)         // 184912
#define SM_TOTAL (SM_CS + 34 * XSTR * 4 + 64)        // ~202584

// ---------------- helpers ----------------
static __device__ __forceinline__ uint32_t smem_u32(const void* p) {
    uint32_t a;
    asm("{ .reg .u64 t; cvta.to.shared.u64 t, %1; cvt.u32.u64 %0, t; }" : "=r"(a) : "l"(p));
    return a;
}
static __device__ __forceinline__ uint32_t cvt_bf16x2(float hi, float lo) {
    uint32_t r;  // d.hi = first operand, d.lo = second operand
    asm("cvt.rn.bf16x2.f32 %0, %1, %2;" : "=r"(r) : "f"(hi), "f"(lo));
    return r;
}
static __device__ __forceinline__ void ldsm_x4(uint32_t a[4], uint32_t addr) {
    asm volatile("ldmatrix.sync.aligned.m8n8.x4.shared.b16 {%0,%1,%2,%3}, [%4];"
                 : "=r"(a[0]), "=r"(a[1]), "=r"(a[2]), "=r"(a[3]) : "r"(addr));
}
static __device__ __forceinline__ void lds_v2(uint32_t& b0, uint32_t& b1, uint32_t addr) {
    asm volatile("ld.shared.v2.u32 {%0,%1}, [%2];" : "=r"(b0), "=r"(b1) : "r"(addr));
}
static __device__ __forceinline__ void mma_bf16(float d[4], const uint32_t a[4],
                                                uint32_t b0, uint32_t b1) {
    asm volatile(
        "mma.sync.aligned.m16n8k16.row.col.f32.bf16.bf16.f32 "
        "{%0,%1,%2,%3}, {%4,%5,%6,%7}, {%8,%9}, {%0,%1,%2,%3};"
        : "+f"(d[0]), "+f"(d[1]), "+f"(d[2]), "+f"(d[3])
        : "r"(a[0]), "r"(a[1]), "r"(a[2]), "r"(a[3]), "r"(b0), "r"(b1));
}

// ---------------- prep: build fragment-linear split-bf16 W ----------------
// W'[k][o]: k<561 -> ch=k/17, i=k%17; ch<32: cond_weight[h][o*17+i][ch]; ch==32: cond_bias
static __device__ __forceinline__ float wval(const float* cw, const float* cb,
                                             int h, int k, int o) {
    if (k >= KREAL) return 0.0f;
    int ch = k / 17, i = k - ch * 17;
    return (ch < 32) ? cw[((h * 544) + o * 17 + i) * 32 + ch]
                     : cb[h * 544 + o * 17 + i];
}
__global__ void mml_prep_k(const float* __restrict__ cw, const float* __restrict__ cb) {
    int idx = blockIdx.x * blockDim.x + threadIdx.x;   // one (h,s,ks,nt,lane)
    if (idx >= H * 2 * NKSTEP * 4 * 32) return;
    int lane = idx & 31;
    int nt   = (idx >> 5) & 3;
    int ks   = (idx >> 7) % NKSTEP;
    int sh   = (idx >> 7) / NKSTEP;
    int s    = sh & 1;
    int h    = sh >> 1;
    int g = lane >> 2, t = lane & 3;
    int o = nt * 8 + g;
#pragma unroll
    for (int j = 0; j < 2; j++) {
        int k0 = ks * 16 + 2 * t + 8 * j;
        uint32_t bits[2];
#pragma unroll
        for (int e = 0; e < 2; e++) {
            float w = wval(cw, cb, h, k0 + e, o);
            __nv_bfloat16 bh = __float2bfloat16(w);
            __nv_bfloat16 v = (s == 0) ? bh : __float2bfloat16(w - __bfloat162float(bh));
            bits[e] = (uint32_t)__bfloat16_as_ushort(v);
        }
        g_wf[(size_t)idx * 2 + j] = bits[0] | (bits[1] << 16);
    }
}

// ---------------- main: fused P-gen + mma.sync GEMM ----------------
__global__ void __launch_bounds__(256, 1)
mml_mma_k(const float* __restrict__ input, const float* __restrict__ cond,
          float* __restrict__ out) {
    extern __shared__ char smem[];
    const int tid = threadIdx.x;
    const int wid = tid >> 5;
    const int lane = tid & 31;
    const int h = blockIdx.y;
    const int blk = blockIdx.x;

    // --- prologue: W fragments -> smem (plain 16B copy) ---
    {
        const uint4* src = reinterpret_cast<const uint4*>(g_wf + (size_t)h * WF_U32_PER_HEAD);
        uint4* dst = reinterpret_cast<uint4*>(smem + SM_WF);
#pragma unroll 1
        for (int t = tid; t < WF_BYTES / 16; t += 256) dst[t] = src[t];
    }
    // --- x / cond transposed into smem (odd stride => conflict-free) ---
    {
        float* xs = reinterpret_cast<float*>(smem + SM_XS);
        float* cs = reinterpret_cast<float*>(smem + SM_CS);
        const float* xg = input + (size_t)(h * Bn + blk * MTILE) * INF;
        const float* cg = cond + (size_t)(h * Bn + blk * MTILE) * CI;
#pragma unroll 1
        for (int t = tid; t < MTILE * INF; t += 256) {
            int m = t >> 4, i = t & 15;
            xs[i * XSTR + m] = xg[t];
        }
#pragma unroll 1
        for (int t = tid; t < MTILE * CI; t += 256) {
            int m = t >> 5, c = t & 31;
            cs[c * XSTR + m] = cg[t];
        }
        if (tid < MTILE) {
            xs[16 * XSTR + tid] = 1.0f;   // homogeneous input
            cs[32 * XSTR + tid] = 1.0f;   // bias channel
            cs[33 * XSTR + tid] = 0.0f;   // zero pad channel (k 561..575)
        }
    }
    __syncthreads();

    // accumulators: 4 n-tiles x 4 f32 frags
    float d[4][4];
#pragma unroll
    for (int n = 0; n < 4; n++)
#pragma unroll
        for (int e = 0; e < 4; e++) d[n][e] = 0.0f;

    // gen-role constants: thread owns sample m, half hf of each chunk's K
    const int m = tid & 127;
    const int hf = tid >> 7;
    const float* xsm = reinterpret_cast<const float*>(smem + SM_XS) + m;
    const float* csm = reinterpret_cast<const float*>(smem + SM_CS) + m;

    // mma-role constants
    const uint32_t sb = smem_u32(smem);
    const int m0 = wid * 16;
    const int mat = lane >> 3, rin = lane & 7;
    const uint32_t a_off = (uint32_t)((m0 + rin + (mat & 1) * 8) * PROW + (mat >> 1) * 16);
    const uint32_t ph_addr = sb + SM_PH + a_off;
    const uint32_t pl_addr = sb + SM_PL + a_off;
    const uint32_t wf_lane = sb + SM_WF + (uint32_t)lane * 8;

#pragma unroll 1
    for (int c = 0; c < NCHUNK; c++) {
        // ---- generate P chunk: 96 k per thread, split hi/lo, pack pairs ----
        {
            int kb = c * CHUNK_K + hf * 96;
            int ch = kb / 17;
            int ii = kb - ch * 17;
            float cv = csm[ch * XSTR];
            uint4* phrow = reinterpret_cast<uint4*>(smem + SM_PH + m * PROW + hf * 192);
            uint4* plrow = reinterpret_cast<uint4*>(smem + SM_PL + m * PROW + hf * 192);
#pragma unroll
            for (int j8 = 0; j8 < 12; j8++) {
                uint32_t hr[4], lr[4];
#pragma unroll
                for (int u = 0; u < 4; u++) {
                    float p0 = cv * xsm[ii * XSTR];
                    ii++; if (ii == 17) { ii = 0; ch++; cv = csm[ch * XSTR]; }
                    float p1 = cv * xsm[ii * XSTR];
                    ii++; if (ii == 17) { ii = 0; ch++; cv = csm[ch * XSTR]; }
                    uint32_t hi = cvt_bf16x2(p1, p0);
                    float h0 = __uint_as_float(hi << 16);
                    float h1 = __uint_as_float(hi & 0xFFFF0000u);
                    uint32_t lo = cvt_bf16x2(p1 - h1, p0 - h0);
                    hr[u] = hi; lr[u] = lo;
                }
                phrow[j8] = make_uint4(hr[0], hr[1], hr[2], hr[3]);
                plrow[j8] = make_uint4(lr[0], lr[1], lr[2], lr[3]);
            }
        }
        __syncthreads();

        // ---- consume chunk: each warp does its 16-row m-tile ----
#pragma unroll
        for (int ks = 0; ks < KSC; ks++) {
            const int ksg = c * KSC + ks;
            uint32_t ah[4], al[4];
            ldsm_x4(ah, ph_addr + ks * 32);
            ldsm_x4(al, pl_addr + ks * 32);
#pragma unroll
            for (int nt = 0; nt < 4; nt++) {
                uint32_t woff = wf_lane + (uint32_t)((ksg * 4 + nt) * 256);
                uint32_t bh0, bh1, bl0, bl1;
                lds_v2(bh0, bh1, woff);                      // split hi
                lds_v2(bl0, bl1, woff + (uint32_t)WF_BYTES / 2);  // split lo
                mma_bf16(d[nt], ah, bh0, bh1);   // Ph * Wh
                mma_bf16(d[nt], al, bh0, bh1);   // Pl * Wh
                mma_bf16(d[nt], ah, bl0, bl1);   // Ph * Wl
            }
        }
        __syncthreads();
    }

    // ---- epilogue: write D fragments ----
    {
        const int g = lane >> 2, t4 = lane & 3;
        const size_t base = (size_t)(h * Bn + blk * MTILE);
#pragma unroll
        for (int nt = 0; nt < 4; nt++) {
            int col = nt * 8 + 2 * t4;
            float2 v0 = make_float2(d[nt][0], d[nt][1]);   // row m0+g
            float2 v1 = make_float2(d[nt][2], d[nt][3]);   // row m0+g+8
            *reinterpret_cast<float2*>(out + (base + m0 + g) * OF + col) = v0;
            *reinterpret_cast<float2*>(out + (base + m0 + g + 8) * OF + col) = v1;
        }
    }
}

extern "C" void kernel_launch(void* const* d_in, const int* in_sizes, int n_in,
                              void* d_out, int out_size) {
    const float* input = (const float*)d_in[0];   // (8, 32768, 16)
    const float* cond  = (const float*)d_in[1];   // (8, 32768, 32)
    const float* cw    = (const float*)d_in[2];   // (8, 544, 32)
    const float* cb    = (const float*)d_in[3];   // (8, 544)
    float* out = (float*)d_out;                   // (8, 32768, 32)

    int prep_threads = H * 2 * NKSTEP * 4 * 32;   // 73728
    mml_prep_k<<<(prep_threads + 255) / 256, 256>>>(cw, cb);

    cudaFuncSetAttribute(mml_mma_k, cudaFuncAttributeMaxDynamicSharedMemorySize, SM_TOTAL);
    dim3 grid(Bn / MTILE, H);                     // (256, 8)
    mml_mma_k<<<grid, 256, SM_TOTAL>>>(input, cond, out);
}

// round 5
// speedup vs baseline: 1.0018x; 1.0018x over previous
#include <cuda_runtime.h>
#include <cuda_bf16.h>
#include <cstdint>

// ---------------- problem constants ----------------
#define H     8
#define Bn    32768
#define INF   16
#define CI    32
#define OF    32
#define KREAL 561          // 33 channels * 17 inputs (33*17 == 561 exactly)
#define KPAD  576          // 36 k-steps of 16
#define NKSTEP 36
#define MTILE 128          // samples per CTA
#define CHUNK_K 192        // K per staged chunk
#define NCHUNK 3
#define KSC   12           // ksteps per chunk

// fragment-linear W in device-global scratch:
// u32 index = (((h*2 + s)*NKSTEP + ks)*4 + nt)*32*2 + lane*2 + j   (j: b0/b1)
#define WF_U32_PER_HEAD (2 * NKSTEP * 4 * 32 * 2)   // 18432
__device__ uint32_t g_wf[H * WF_U32_PER_HEAD];

// ---------------- smem layout (bytes) ----------------
#define SM_WF   0
#define WF_BYTES (WF_U32_PER_HEAD * 4)              // 73728
#define PROW    400                                  // 192 bf16 = 384B + 16B pad (16B-mult, stride%32banks=4)
#define SM_PH   (SM_WF + WF_BYTES)                   // 73728
#define SM_PL   (SM_PH + MTILE * PROW)               // 124928
#define SM_XS   (SM_PL + MTILE * PROW)               // 176128
#define XSTR    129                                  // float stride (odd -> conflict-free transpose fill)
#define SM_CS   (SM_XS + 17 * XSTR * 4 + 12)         // 184912
#define SM_TOTAL (SM_CS + 34 * XSTR * 4 + 64)        // ~202584

// ---------------- helpers ----------------
static __device__ __forceinline__ uint32_t smem_u32(const void* p) {
    uint32_t a;
    asm("{ .reg .u64 t; cvta.to.shared.u64 t, %1; cvt.u32.u64 %0, t; }" : "=r"(a) : "l"(p));
    return a;
}
static __device__ __forceinline__ uint32_t cvt_bf16x2(float hi, float lo) {
    uint32_t r;  // d.hi = first operand, d.lo = second operand
    asm("cvt.rn.bf16x2.f32 %0, %1, %2;" : "=r"(r) : "f"(hi), "f"(lo));
    return r;
}
static __device__ __forceinline__ void ldsm_x4(uint32_t a[4], uint32_t addr) {
    asm volatile("ldmatrix.sync.aligned.m8n8.x4.shared.b16 {%0,%1,%2,%3}, [%4];"
                 : "=r"(a[0]), "=r"(a[1]), "=r"(a[2]), "=r"(a[3]) : "r"(addr));
}
static __device__ __forceinline__ void lds_v2(uint32_t& b0, uint32_t& b1, uint32_t addr) {
    asm volatile("ld.shared.v2.u32 {%0,%1}, [%2];" : "=r"(b0), "=r"(b1) : "r"(addr));
}
static __device__ __forceinline__ void mma_bf16(float d[4], const uint32_t a[4],
                                                uint32_t b0, uint32_t b1) {
    asm volatile(
        "mma.sync.aligned.m16n8k16.row.col.f32.bf16.bf16.f32 "
        "{%0,%1,%2,%3}, {%4,%5,%6,%7}, {%8,%9}, {%0,%1,%2,%3};"
        : "+f"(d[0]), "+f"(d[1]), "+f"(d[2]), "+f"(d[3])
        : "r"(a[0]), "r"(a[1]), "r"(a[2]), "r"(a[3]), "r"(b0), "r"(b1));
}

// ---------------- prep: build fragment-linear split-bf16 W ----------------
// W'[k][o]: k<561 -> ch=k/17, i=k%17; ch<32: cond_weight[h][o*17+i][ch]; ch==32: cond_bias
static __device__ __forceinline__ float wval(const float* cw, const float* cb,
                                             int h, int k, int o) {
    if (k >= KREAL) return 0.0f;
    int ch = k / 17, i = k - ch * 17;
    return (ch < 32) ? cw[((h * 544) + o * 17 + i) * 32 + ch]
                     : cb[h * 544 + o * 17 + i];
}
__global__ void mml_prep_k(const float* __restrict__ cw, const float* __restrict__ cb) {
    int idx = blockIdx.x * blockDim.x + threadIdx.x;   // one (h,s,ks,nt,lane)
    if (idx >= H * 2 * NKSTEP * 4 * 32) return;
    int lane = idx & 31;
    int nt   = (idx >> 5) & 3;
    int ks   = (idx >> 7) % NKSTEP;
    int sh   = (idx >> 7) / NKSTEP;
    int s    = sh & 1;
    int h    = sh >> 1;
    int g = lane >> 2, t = lane & 3;
    int o = nt * 8 + g;
#pragma unroll
    for (int j = 0; j < 2; j++) {
        int k0 = ks * 16 + 2 * t + 8 * j;
        uint32_t bits[2];
#pragma unroll
        for (int e = 0; e < 2; e++) {
            float w = wval(cw, cb, h, k0 + e, o);
            __nv_bfloat16 bh = __float2bfloat16(w);
            __nv_bfloat16 v = (s == 0) ? bh : __float2bfloat16(w - __bfloat162float(bh));
            bits[e] = (uint32_t)__bfloat16_as_ushort(v);
        }
        g_wf[(size_t)idx * 2 + j] = bits[0] | (bits[1] << 16);
    }
}

// ---------------- main: fused P-gen + mma.sync GEMM ----------------
__global__ void __launch_bounds__(256, 1)
mml_mma_k(const float* __restrict__ input, const float* __restrict__ cond,
          float* __restrict__ out) {
    extern __shared__ char smem[];
    const int tid = threadIdx.x;
    const int wid = tid >> 5;
    const int lane = tid & 31;
    const int h = blockIdx.y;
    const int blk = blockIdx.x;

    // --- prologue: W fragments -> smem (plain 16B copy) ---
    {
        const uint4* src = reinterpret_cast<const uint4*>(g_wf + (size_t)h * WF_U32_PER_HEAD);
        uint4* dst = reinterpret_cast<uint4*>(smem + SM_WF);
#pragma unroll 1
        for (int t = tid; t < WF_BYTES / 16; t += 256) dst[t] = src[t];
    }
    // --- x / cond transposed into smem (odd stride => conflict-free) ---
    {
        float* xs = reinterpret_cast<float*>(smem + SM_XS);
        float* cs = reinterpret_cast<float*>(smem + SM_CS);
        const float* xg = input + (size_t)(h * Bn + blk * MTILE) * INF;
        const float* cg = cond + (size_t)(h * Bn + blk * MTILE) * CI;
#pragma unroll 1
        for (int t = tid; t < MTILE * INF; t += 256) {
            int m = t >> 4, i = t & 15;
            xs[i * XSTR + m] = xg[t];
        }
#pragma unroll 1
        for (int t = tid; t < MTILE * CI; t += 256) {
            int m = t >> 5, c = t & 31;
            cs[c * XSTR + m] = cg[t];
        }
        if (tid < MTILE) {
            xs[16 * XSTR + tid] = 1.0f;   // homogeneous input
            cs[32 * XSTR + tid] = 1.0f;   // bias channel
            cs[33 * XSTR + tid] = 0.0f;   // zero pad channel (k 561..575)
        }
    }
    __syncthreads();

    // accumulators: 4 n-tiles x 4 f32 frags
    float d[4][4];
#pragma unroll
    for (int n = 0; n < 4; n++)
#pragma unroll
        for (int e = 0; e < 4; e++) d[n][e] = 0.0f;

    // gen-role constants: thread owns sample m, half hf of each chunk's K
    const int m = tid & 127;
    const int hf = tid >> 7;
    const float* xsm = reinterpret_cast<const float*>(smem + SM_XS) + m;
    const float* csm = reinterpret_cast<const float*>(smem + SM_CS) + m;

    // mma-role constants
    const uint32_t sb = smem_u32(smem);
    const int m0 = wid * 16;
    const int mat = lane >> 3, rin = lane & 7;
    const uint32_t a_off = (uint32_t)((m0 + rin + (mat & 1) * 8) * PROW + (mat >> 1) * 16);
    const uint32_t ph_addr = sb + SM_PH + a_off;
    const uint32_t pl_addr = sb + SM_PL + a_off;
    const uint32_t wf_lane = sb + SM_WF + (uint32_t)lane * 8;

#pragma unroll 1
    for (int c = 0; c < NCHUNK; c++) {
        // ---- generate P chunk: 96 k per thread, split hi/lo, pack pairs ----
        {
            int kb = c * CHUNK_K + hf * 96;
            int ch = kb / 17;
            int ii = kb - ch * 17;
            float cv = csm[ch * XSTR];
            uint4* phrow = reinterpret_cast<uint4*>(smem + SM_PH + m * PROW + hf * 192);
            uint4* plrow = reinterpret_cast<uint4*>(smem + SM_PL + m * PROW + hf * 192);
#pragma unroll
            for (int j8 = 0; j8 < 12; j8++) {
                uint32_t hr[4], lr[4];
#pragma unroll
                for (int u = 0; u < 4; u++) {
                    float p0 = cv * xsm[ii * XSTR];
                    ii++; if (ii == 17) { ii = 0; ch++; cv = csm[ch * XSTR]; }
                    float p1 = cv * xsm[ii * XSTR];
                    ii++; if (ii == 17) { ii = 0; ch++; cv = csm[ch * XSTR]; }
                    uint32_t hi = cvt_bf16x2(p1, p0);
                    float h0 = __uint_as_float(hi << 16);
                    float h1 = __uint_as_float(hi & 0xFFFF0000u);
                    uint32_t lo = cvt_bf16x2(p1 - h1, p0 - h0);
                    hr[u] = hi; lr[u] = lo;
                }
                phrow[j8] = make_uint4(hr[0], hr[1], hr[2], hr[3]);
                plrow[j8] = make_uint4(lr[0], lr[1], lr[2], lr[3]);
            }
        }
        __syncthreads();

        // ---- consume chunk: each warp does its 16-row m-tile ----
#pragma unroll
        for (int ks = 0; ks < KSC; ks++) {
            const int ksg = c * KSC + ks;
            uint32_t ah[4], al[4];
            ldsm_x4(ah, ph_addr + ks * 32);
            ldsm_x4(al, pl_addr + ks * 32);
#pragma unroll
            for (int nt = 0; nt < 4; nt++) {
                uint32_t woff = wf_lane + (uint32_t)((ksg * 4 + nt) * 256);
                uint32_t bh0, bh1, bl0, bl1;
                lds_v2(bh0, bh1, woff);                      // split hi
                lds_v2(bl0, bl1, woff + (uint32_t)WF_BYTES / 2);  // split lo
                mma_bf16(d[nt], ah, bh0, bh1);   // Ph * Wh
                mma_bf16(d[nt], al, bh0, bh1);   // Pl * Wh
                mma_bf16(d[nt], ah, bl0, bl1);   // Ph * Wl
            }
        }
        __syncthreads();
    }

    // ---- epilogue: write D fragments ----
    {
        const int g = lane >> 2, t4 = lane & 3;
        const size_t base = (size_t)(h * Bn + blk * MTILE);
#pragma unroll
        for (int nt = 0; nt < 4; nt++) {
            int col = nt * 8 + 2 * t4;
            float2 v0 = make_float2(d[nt][0], d[nt][1]);   // row m0+g
            float2 v1 = make_float2(d[nt][2], d[nt][3]);   // row m0+g+8
            *reinterpret_cast<float2*>(out + (base + m0 + g) * OF + col) = v0;
            *reinterpret_cast<float2*>(out + (base + m0 + g + 8) * OF + col) = v1;
        }
    }
}

extern "C" void kernel_launch(void* const* d_in, const int* in_sizes, int n_in,
                              void* d_out, int out_size) {
    const float* input = (const float*)d_in[0];   // (8, 32768, 16)
    const float* cond  = (const float*)d_in[1];   // (8, 32768, 32)
    const float* cw    = (const float*)d_in[2];   // (8, 544, 32)
    const float* cb    = (const float*)d_in[3];   // (8, 544)
    float* out = (float*)d_out;                   // (8, 32768, 32)

    int prep_threads = H * 2 * NKSTEP * 4 * 32;   // 73728
    mml_prep_k<<<(prep_threads + 255) / 256, 256>>>(cw, cb);

    cudaFuncSetAttribute(mml_mma_k, cudaFuncAttributeMaxDynamicSharedMemorySize, SM_TOTAL);
    dim3 grid(Bn / MTILE, H);                     // (256, 8)
    mml_mma_k<<<grid, 256, SM_TOTAL>>>(input, cond, out);
}

// round 6
// speedup vs baseline: 2.3064x; 2.3022x over previous
#include <cuda_runtime.h>
#include <cuda_bf16.h>
#include <cstdint>

#define H    8
#define Bn   32768
#define OF   32
#define NKS  36            // ksteps of 16 -> K = 576
#define KSC  6             // ksteps per chunk
#define NCH  6             // chunks (96 k each)

// W fragments, packed for LDG.128: uint4 idx = (((h*2+s)*NKS+ks)*2+ntp)*32+lane
// uint4 = { nt=2ntp:(b0,b1), nt=2ntp+1:(b0,b1) }
__device__ uint4 g_wf4[H * 2 * NKS * 2 * 32];

// smem: P chunk (hi+lo) + cond
#define PROW   208                     // 96k*2B + 16 pad; 52-word stride: 8-lane phases conflict-free
#define PSPLIT (128 * PROW)            // 26624
#define SM_CS  (2 * PSPLIT)            // 53248
#define CSTR   129
#define SM_TOTAL (SM_CS + 32 * CSTR * 4)   // 69760

static __device__ __forceinline__ uint32_t smem_u32(const void* p) {
    uint32_t a;
    asm("{ .reg .u64 t; cvta.to.shared.u64 t, %1; cvt.u32.u64 %0, t; }" : "=r"(a) : "l"(p));
    return a;
}
static __device__ __forceinline__ uint32_t cvt_bf16x2(float hi, float lo) {
    uint32_t r;
    asm("cvt.rn.bf16x2.f32 %0, %1, %2;" : "=r"(r) : "f"(hi), "f"(lo));
    return r;
}
static __device__ __forceinline__ void split2(float p0, float p1, uint32_t& hi, uint32_t& lo) {
    hi = cvt_bf16x2(p1, p0);
    float h0 = __uint_as_float(hi << 16);
    float h1 = __uint_as_float(hi & 0xFFFF0000u);
    lo = cvt_bf16x2(p1 - h1, p0 - h0);
}
static __device__ __forceinline__ void gen_ch(float cv, const float* xr, char* hd, char* ld) {
    uint32_t hi[8], lo[8];
#pragma unroll
    for (int j = 0; j < 8; j++) split2(cv * xr[2 * j], cv * xr[2 * j + 1], hi[j], lo[j]);
    reinterpret_cast<uint4*>(hd)[0] = make_uint4(hi[0], hi[1], hi[2], hi[3]);
    reinterpret_cast<uint4*>(hd)[1] = make_uint4(hi[4], hi[5], hi[6], hi[7]);
    reinterpret_cast<uint4*>(ld)[0] = make_uint4(lo[0], lo[1], lo[2], lo[3]);
    reinterpret_cast<uint4*>(ld)[1] = make_uint4(lo[4], lo[5], lo[6], lo[7]);
}
static __device__ __forceinline__ void ldsm_x4(uint32_t a[4], uint32_t addr) {
    asm volatile("ldmatrix.sync.aligned.m8n8.x4.shared.b16 {%0,%1,%2,%3}, [%4];"
                 : "=r"(a[0]), "=r"(a[1]), "=r"(a[2]), "=r"(a[3]) : "r"(addr));
}
static __device__ __forceinline__ void mma_bf16(float d[4], const uint32_t a[4],
                                                uint32_t b0, uint32_t b1) {
    asm volatile(
        "mma.sync.aligned.m16n8k16.row.col.f32.bf16.bf16.f32 "
        "{%0,%1,%2,%3}, {%4,%5,%6,%7}, {%8,%9}, {%0,%1,%2,%3};"
        : "+f"(d[0]), "+f"(d[1]), "+f"(d[2]), "+f"(d[3])
        : "r"(a[0]), "r"(a[1]), "r"(a[2]), "r"(a[3]), "r"(b0), "r"(b1));
}

// permuted W': kp<512: W[o*17+(kp&15)][ch=kp>>4]; 512+i: bias(i); 528+q: W[o*17+16][q];
//              560: bias(16); else 0
static __device__ __forceinline__ float wval(const float* cw, const float* cb,
                                             int h, int kp, int o) {
    if (kp < 512) { int ch = kp >> 4, i = kp & 15; return cw[(h * 544 + o * 17 + i) * 32 + ch]; }
    if (kp < 528) return cb[h * 544 + o * 17 + (kp - 512)];
    if (kp < 560) return cw[(h * 544 + o * 17 + 16) * 32 + (kp - 528)];
    if (kp == 560) return cb[h * 544 + o * 17 + 16];
    return 0.0f;
}
__global__ void mml_prep_k(const float* __restrict__ cw, const float* __restrict__ cb) {
    int idx = blockIdx.x * blockDim.x + threadIdx.x;
    if (idx >= H * 2 * NKS * 2 * 32) return;
    int lane = idx & 31;
    int ntp  = (idx >> 5) & 1;
    int ks   = (idx >> 6) % NKS;
    int sh   = (idx >> 6) / NKS;
    int s = sh & 1, h = sh >> 1;
    int g = lane >> 2, t = lane & 3;
    uint32_t v[4];
#pragma unroll
    for (int p = 0; p < 2; p++) {
        int o = (ntp * 2 + p) * 8 + g;
#pragma unroll
        for (int j = 0; j < 2; j++) {
            int k0 = ks * 16 + 2 * t + 8 * j;
            uint32_t b[2];
#pragma unroll
            for (int e = 0; e < 2; e++) {
                float w = wval(cw, cb, h, k0 + e, o);
                __nv_bfloat16 bh = __float2bfloat16(w);
                __nv_bfloat16 vv = (s == 0) ? bh : __float2bfloat16(w - __bfloat162float(bh));
                b[e] = (uint32_t)__bfloat16_as_ushort(vv);
            }
            v[p * 2 + j] = b[0] | (b[1] << 16);
        }
    }
    g_wf4[idx] = make_uint4(v[0], v[1], v[2], v[3]);
}

__global__ void __launch_bounds__(256, 2)
mml_k(const float* __restrict__ input, const float* __restrict__ cond,
      float* __restrict__ out) {
    extern __shared__ char smem[];
    const uint32_t sbp = smem_u32(smem);
    const int tid = threadIdx.x;
    const int wid = tid >> 5;
    const int lane = tid & 31;
    const int h = blockIdx.y;
    const size_t sbase = (size_t)(h * Bn + blockIdx.x * 128);

    // cond -> cs[ch][m] (stride 129, conflict-free both ways)
    float* cs = reinterpret_cast<float*>(smem + SM_CS);
    {
        const float* cg = cond + sbase * 32;
#pragma unroll 1
        for (int t = tid; t < 128 * 32; t += 256) cs[(t & 31) * CSTR + (t >> 5)] = cg[t];
    }
    // per-thread x registers (sample m; both hf halves hold the same sample's x)
    const int m = tid & 127;
    const int hf = tid >> 7;
    float xr[16];
    {
        const float4* xg = reinterpret_cast<const float4*>(input + (sbase + m) * 16);
#pragma unroll
        for (int q = 0; q < 4; q++) {
            float4 v = xg[q];
            xr[q * 4] = v.x; xr[q * 4 + 1] = v.y; xr[q * 4 + 2] = v.z; xr[q * 4 + 3] = v.w;
        }
    }
    __syncthreads();

    float dm[4][4], dc[4][4];
#pragma unroll
    for (int n = 0; n < 4; n++)
#pragma unroll
        for (int e = 0; e < 4; e++) { dm[n][e] = 0.0f; dc[n][e] = 0.0f; }

    // consumer addressing
    const int m0 = wid * 16;
    const int mat = lane >> 3, rin = lane & 7;
    const uint32_t a_off = (uint32_t)((m0 + rin + (mat & 1) * 8) * PROW + (mat >> 1) * 16);
    const uint32_t ph_addr = sbp + a_off;
    const uint32_t pl_addr = ph_addr + PSPLIT;
    const uint4* wH = g_wf4 + ((size_t)(h * 2 + 0) * NKS * 2) * 32 + lane;
    const uint4* wL = g_wf4 + ((size_t)(h * 2 + 1) * NKS * 2) * 32 + lane;
    const float* csm = cs + m;

#pragma unroll 1
    for (int c = 0; c < NCH; c++) {
        // ---- gen this thread's 48-k half of the 96-k chunk ----
        char* ph = smem + m * PROW + hf * 96;
        char* pl = ph + PSPLIT;
        if (c < 5) {
            const int ch0 = c * 6 + hf * 3;
            gen_ch(csm[(ch0 + 0) * CSTR], xr, ph, pl);
            gen_ch(csm[(ch0 + 1) * CSTR], xr, ph + 32, pl + 32);
            gen_ch(csm[(ch0 + 2) * CSTR], xr, ph + 64, pl + 64);
        } else if (hf == 0) {
            gen_ch(csm[30 * CSTR], xr, ph, pl);
            gen_ch(csm[31 * CSTR], xr, ph + 32, pl + 32);
            gen_ch(1.0f, xr, ph + 64, pl + 64);               // bias rows: P = x[i]
        } else {
            uint32_t hi[16], lo[16];
#pragma unroll
            for (int j = 0; j < 16; j++)
                split2(csm[(2 * j) * CSTR], csm[(2 * j + 1) * CSTR], hi[j], lo[j]);
#pragma unroll
            for (int q = 0; q < 4; q++) {
                reinterpret_cast<uint4*>(ph)[q] =
                    make_uint4(hi[4 * q], hi[4 * q + 1], hi[4 * q + 2], hi[4 * q + 3]);
                reinterpret_cast<uint4*>(pl)[q] =
                    make_uint4(lo[4 * q], lo[4 * q + 1], lo[4 * q + 2], lo[4 * q + 3]);
            }
            // kp 560 = 1.0 (bf16 0x3F80 in low half), 561..575 = 0
            reinterpret_cast<uint4*>(ph)[4] = make_uint4(0x3F80u, 0, 0, 0);
            reinterpret_cast<uint4*>(ph)[5] = make_uint4(0, 0, 0, 0);
            reinterpret_cast<uint4*>(pl)[4] = make_uint4(0, 0, 0, 0);
            reinterpret_cast<uint4*>(pl)[5] = make_uint4(0, 0, 0, 0);
        }
        __syncthreads();

        // ---- consume chunk: 6 ksteps, W via coalesced L1/L2-hit LDG.128 ----
#pragma unroll
        for (int ks = 0; ks < KSC; ks++) {
            const int ksg = c * KSC + ks;
            uint32_t ah[4], al[4];
            ldsm_x4(ah, ph_addr + (uint32_t)(ks * 32));
            ldsm_x4(al, pl_addr + (uint32_t)(ks * 32));
            uint4 whA = wH[(ksg * 2 + 0) * 32];
            uint4 whB = wH[(ksg * 2 + 1) * 32];
            uint4 wlA = wL[(ksg * 2 + 0) * 32];
            uint4 wlB = wL[(ksg * 2 + 1) * 32];
            mma_bf16(dm[0], ah, whA.x, whA.y);
            mma_bf16(dm[1], ah, whA.z, whA.w);
            mma_bf16(dm[2], ah, whB.x, whB.y);
            mma_bf16(dm[3], ah, whB.z, whB.w);
            mma_bf16(dc[0], al, whA.x, whA.y);
            mma_bf16(dc[1], al, whA.z, whA.w);
            mma_bf16(dc[2], al, whB.x, whB.y);
            mma_bf16(dc[3], al, whB.z, whB.w);
            mma_bf16(dc[0], ah, wlA.x, wlA.y);
            mma_bf16(dc[1], ah, wlA.z, wlA.w);
            mma_bf16(dc[2], ah, wlB.x, wlB.y);
            mma_bf16(dc[3], ah, wlB.z, wlB.w);
        }
        __syncthreads();
    }

    // ---- epilogue ----
    {
        const int g = lane >> 2, t4 = lane & 3;
#pragma unroll
        for (int nt = 0; nt < 4; nt++) {
            int col = nt * 8 + 2 * t4;
            float2 v0 = make_float2(dm[nt][0] + dc[nt][0], dm[nt][1] + dc[nt][1]);
            float2 v1 = make_float2(dm[nt][2] + dc[nt][2], dm[nt][3] + dc[nt][3]);
            *reinterpret_cast<float2*>(out + (sbase + m0 + g) * OF + col) = v0;
            *reinterpret_cast<float2*>(out + (sbase + m0 + g + 8) * OF + col) = v1;
        }
    }
}

extern "C" void kernel_launch(void* const* d_in, const int* in_sizes, int n_in,
                              void* d_out, int out_size) {
    const float* input = (const float*)d_in[0];
    const float* cond  = (const float*)d_in[1];
    const float* cw    = (const float*)d_in[2];
    const float* cb    = (const float*)d_in[3];
    float* out = (float*)d_out;

    int prep = H * 2 * NKS * 2 * 32;   // 36864
    mml_prep_k<<<(prep + 255) / 256, 256>>>(cw, cb);

    cudaFuncSetAttribute(mml_k, cudaFuncAttributeMaxDynamicSharedMemorySize, SM_TOTAL);
    dim3 grid(Bn / 128, H);            // (256, 8)
    mml_k<<<grid, 256, SM_TOTAL>>>(input, cond, out);
}

// round 7
// speedup vs baseline: 2.3082x; 1.0008x over previous
#include <cuda_runtime.h>
#include <cuda_bf16.h>
#include <cstdint>

#define H    8
#define Bn   32768
#define OF   32
#define NKS  36            // ksteps of 16 -> K = 576
#define KSC  4             // ksteps per chunk
#define NCH  9             // chunks (64 k each)

// W fragments, packed for LDG.128: uint4 idx = (((h*2+s)*NKS+ks)*2+ntp)*32+lane
__device__ uint4 g_wf4[H * 2 * NKS * 2 * 32];

// smem: 2 P buffers (each: hi plane + lo plane) + cond
#define PROW   144                     // 64k*2B + 16 pad (36-word stride: conflict-free)
#define PSPLIT (128 * PROW)            // 18432
#define PBUF   (2 * PSPLIT)            // 36864
#define SM_CS  (2 * PBUF)              // 73728
#define CSTR   129
#define SM_TOTAL (SM_CS + 32 * CSTR * 4)   // 90240

static __device__ __forceinline__ uint32_t smem_u32(const void* p) {
    uint32_t a;
    asm("{ .reg .u64 t; cvta.to.shared.u64 t, %1; cvt.u32.u64 %0, t; }" : "=r"(a) : "l"(p));
    return a;
}
static __device__ __forceinline__ uint32_t cvt_bf16x2(float hi, float lo) {
    uint32_t r;
    asm("cvt.rn.bf16x2.f32 %0, %1, %2;" : "=r"(r) : "f"(hi), "f"(lo));
    return r;
}
static __device__ __forceinline__ void split2(float p0, float p1, uint32_t& hi, uint32_t& lo) {
    hi = cvt_bf16x2(p1, p0);
    float h0 = __uint_as_float(hi << 16);
    float h1 = __uint_as_float(hi & 0xFFFF0000u);
    lo = cvt_bf16x2(p1 - h1, p0 - h0);
}
static __device__ __forceinline__ void gen_ch(float cv, const float* xr, char* hd, char* ld) {
    uint32_t hi[8], lo[8];
#pragma unroll
    for (int j = 0; j < 8; j++) split2(cv * xr[2 * j], cv * xr[2 * j + 1], hi[j], lo[j]);
    reinterpret_cast<uint4*>(hd)[0] = make_uint4(hi[0], hi[1], hi[2], hi[3]);
    reinterpret_cast<uint4*>(hd)[1] = make_uint4(hi[4], hi[5], hi[6], hi[7]);
    reinterpret_cast<uint4*>(ld)[0] = make_uint4(lo[0], lo[1], lo[2], lo[3]);
    reinterpret_cast<uint4*>(ld)[1] = make_uint4(lo[4], lo[5], lo[6], lo[7]);
}
static __device__ __forceinline__ void ldsm_x4(uint32_t a[4], uint32_t addr) {
    asm volatile("ldmatrix.sync.aligned.m8n8.x4.shared.b16 {%0,%1,%2,%3}, [%4];"
                 : "=r"(a[0]), "=r"(a[1]), "=r"(a[2]), "=r"(a[3]) : "r"(addr));
}
static __device__ __forceinline__ void mma_bf16(float d[4], const uint32_t a[4],
                                                uint32_t b0, uint32_t b1) {
    asm volatile(
        "mma.sync.aligned.m16n8k16.row.col.f32.bf16.bf16.f32 "
        "{%0,%1,%2,%3}, {%4,%5,%6,%7}, {%8,%9}, {%0,%1,%2,%3};"
        : "+f"(d[0]), "+f"(d[1]), "+f"(d[2]), "+f"(d[3])
        : "r"(a[0]), "r"(a[1]), "r"(a[2]), "r"(a[3]), "r"(b0), "r"(b1));
}

// permuted W': kp<512: W[o*17+(kp&15)][ch=kp>>4]; 512+i: bias(i); 528+q: W[o*17+16][q];
//              560: bias(16); else 0
static __device__ __forceinline__ float wval(const float* cw, const float* cb,
                                             int h, int kp, int o) {
    if (kp < 512) { int ch = kp >> 4, i = kp & 15; return cw[(h * 544 + o * 17 + i) * 32 + ch]; }
    if (kp < 528) return cb[h * 544 + o * 17 + (kp - 512)];
    if (kp < 560) return cw[(h * 544 + o * 17 + 16) * 32 + (kp - 528)];
    if (kp == 560) return cb[h * 544 + o * 17 + 16];
    return 0.0f;
}
__global__ void mml_prep_k(const float* __restrict__ cw, const float* __restrict__ cb) {
    int idx = blockIdx.x * blockDim.x + threadIdx.x;
    if (idx >= H * 2 * NKS * 2 * 32) return;
    int lane = idx & 31;
    int ntp  = (idx >> 5) & 1;
    int ks   = (idx >> 6) % NKS;
    int sh   = (idx >> 6) / NKS;
    int s = sh & 1, h = sh >> 1;
    int g = lane >> 2, t = lane & 3;
    uint32_t v[4];
#pragma unroll
    for (int p = 0; p < 2; p++) {
        int o = (ntp * 2 + p) * 8 + g;
#pragma unroll
        for (int j = 0; j < 2; j++) {
            int k0 = ks * 16 + 2 * t + 8 * j;
            uint32_t b[2];
#pragma unroll
            for (int e = 0; e < 2; e++) {
                float w = wval(cw, cb, h, k0 + e, o);
                __nv_bfloat16 bh = __float2bfloat16(w);
                __nv_bfloat16 vv = (s == 0) ? bh : __float2bfloat16(w - __bfloat162float(bh));
                b[e] = (uint32_t)__bfloat16_as_ushort(vv);
            }
            v[p * 2 + j] = b[0] | (b[1] << 16);
        }
    }
    g_wf4[idx] = make_uint4(v[0], v[1], v[2], v[3]);
}

__global__ void __launch_bounds__(256, 2)
mml_k(const float* __restrict__ input, const float* __restrict__ cond,
      float* __restrict__ out) {
    extern __shared__ char smem[];
    const uint32_t sbp = smem_u32(smem);
    const int tid = threadIdx.x;
    const int wid = tid >> 5;
    const int lane = tid & 31;
    const int h = blockIdx.y;
    const size_t sbase = (size_t)(h * Bn + blockIdx.x * 128);

    // cond -> cs[ch][m] (stride 129, conflict-free both ways)
    float* cs = reinterpret_cast<float*>(smem + SM_CS);
    {
        const float* cg = cond + sbase * 32;
#pragma unroll 1
        for (int t = tid; t < 128 * 32; t += 256) cs[(t & 31) * CSTR + (t >> 5)] = cg[t];
    }
    // per-thread x registers (sample m)
    const int m = tid & 127;
    const int hf = tid >> 7;
    float xr[16];
    {
        const float4* xg = reinterpret_cast<const float4*>(input + (sbase + m) * 16);
#pragma unroll
        for (int q = 0; q < 4; q++) {
            float4 v = xg[q];
            xr[q * 4] = v.x; xr[q * 4 + 1] = v.y; xr[q * 4 + 2] = v.z; xr[q * 4 + 3] = v.w;
        }
    }
    __syncthreads();

    float dm[4][4], dc[4][4];
#pragma unroll
    for (int n = 0; n < 4; n++)
#pragma unroll
        for (int e = 0; e < 4; e++) { dm[n][e] = 0.0f; dc[n][e] = 0.0f; }

    // consumer addressing
    const int m0 = wid * 16;
    const int mat = lane >> 3, rin = lane & 7;
    const uint32_t a_off = (uint32_t)((m0 + rin + (mat & 1) * 8) * PROW + (mat >> 1) * 16);
    const uint4* wH = g_wf4 + ((size_t)(h * 2 + 0) * NKS * 2) * 32 + lane;
    const uint4* wL = g_wf4 + ((size_t)(h * 2 + 1) * NKS * 2) * 32 + lane;
    const float* csm = cs + m;
    char* genb = smem + m * PROW + hf * 64;   // this thread's gen slot (buffer 0)

    // gen chunk c (4 channels / 64 k) into buffer base gb
    auto gen_chunk = [&](int c, char* ph) {
        char* pl = ph + PSPLIT;
        if (c < 8) {
            const int ch0 = c * 4 + hf * 2;
            gen_ch(csm[ch0 * CSTR], xr, ph, pl);
            gen_ch(csm[(ch0 + 1) * CSTR], xr, ph + 32, pl + 32);
        } else if (hf == 0) {
            gen_ch(1.0f, xr, ph, pl);                    // kp 512..527: P = x[i]
            uint32_t hi[8], lo[8];
#pragma unroll
            for (int j = 0; j < 8; j++)
                split2(csm[(2 * j) * CSTR], csm[(2 * j + 1) * CSTR], hi[j], lo[j]);
            reinterpret_cast<uint4*>(ph + 32)[0] = make_uint4(hi[0], hi[1], hi[2], hi[3]);
            reinterpret_cast<uint4*>(ph + 32)[1] = make_uint4(hi[4], hi[5], hi[6], hi[7]);
            reinterpret_cast<uint4*>(pl + 32)[0] = make_uint4(lo[0], lo[1], lo[2], lo[3]);
            reinterpret_cast<uint4*>(pl + 32)[1] = make_uint4(lo[4], lo[5], lo[6], lo[7]);
        } else {
            uint32_t hi[8], lo[8];
#pragma unroll
            for (int j = 0; j < 8; j++)
                split2(csm[(16 + 2 * j) * CSTR], csm[(17 + 2 * j) * CSTR], hi[j], lo[j]);
            reinterpret_cast<uint4*>(ph)[0] = make_uint4(hi[0], hi[1], hi[2], hi[3]);
            reinterpret_cast<uint4*>(ph)[1] = make_uint4(hi[4], hi[5], hi[6], hi[7]);
            reinterpret_cast<uint4*>(pl)[0] = make_uint4(lo[0], lo[1], lo[2], lo[3]);
            reinterpret_cast<uint4*>(pl)[1] = make_uint4(lo[4], lo[5], lo[6], lo[7]);
            reinterpret_cast<uint4*>(ph + 32)[0] = make_uint4(0x3F80u, 0, 0, 0);  // kp560 = 1.0
            reinterpret_cast<uint4*>(ph + 32)[1] = make_uint4(0, 0, 0, 0);
            reinterpret_cast<uint4*>(pl + 32)[0] = make_uint4(0, 0, 0, 0);
            reinterpret_cast<uint4*>(pl + 32)[1] = make_uint4(0, 0, 0, 0);
        }
    };

    gen_chunk(0, genb);
    __syncthreads();

#pragma unroll 1
    for (int c = 0; c < NCH; c++) {
        // produce next chunk into the other buffer (overlaps with HMMA below)
        if (c + 1 < NCH) gen_chunk(c + 1, genb + ((c + 1) & 1) * PBUF);

        // consume chunk c from buffer c&1
        const uint32_t ph_addr = sbp + (uint32_t)((c & 1) * PBUF) + a_off;
#pragma unroll
        for (int ks = 0; ks < KSC; ks++) {
            const int ksg = c * KSC + ks;
            uint32_t ah[4], al[4];
            ldsm_x4(ah, ph_addr + (uint32_t)(ks * 32));
            ldsm_x4(al, ph_addr + (uint32_t)(PSPLIT + ks * 32));
            uint4 whA = wH[(ksg * 2 + 0) * 32];
            uint4 whB = wH[(ksg * 2 + 1) * 32];
            uint4 wlA = wL[(ksg * 2 + 0) * 32];
            uint4 wlB = wL[(ksg * 2 + 1) * 32];
            mma_bf16(dm[0], ah, whA.x, whA.y);
            mma_bf16(dm[1], ah, whA.z, whA.w);
            mma_bf16(dm[2], ah, whB.x, whB.y);
            mma_bf16(dm[3], ah, whB.z, whB.w);
            mma_bf16(dc[0], al, whA.x, whA.y);
            mma_bf16(dc[1], al, whA.z, whA.w);
            mma_bf16(dc[2], al, whB.x, whB.y);
            mma_bf16(dc[3], al, whB.z, whB.w);
            mma_bf16(dc[0], ah, wlA.x, wlA.y);
            mma_bf16(dc[1], ah, wlA.z, wlA.w);
            mma_bf16(dc[2], ah, wlB.x, wlB.y);
            mma_bf16(dc[3], ah, wlB.z, wlB.w);
        }
        __syncthreads();
    }

    // ---- epilogue ----
    {
        const int g = lane >> 2, t4 = lane & 3;
#pragma unroll
        for (int nt = 0; nt < 4; nt++) {
            int col = nt * 8 + 2 * t4;
            float2 v0 = make_float2(dm[nt][0] + dc[nt][0], dm[nt][1] + dc[nt][1]);
            float2 v1 = make_float2(dm[nt][2] + dc[nt][2], dm[nt][3] + dc[nt][3]);
            *reinterpret_cast<float2*>(out + (sbase + m0 + g) * OF + col) = v0;
            *reinterpret_cast<float2*>(out + (sbase + m0 + g + 8) * OF + col) = v1;
        }
    }
}

extern "C" void kernel_launch(void* const* d_in, const int* in_sizes, int n_in,
                              void* d_out, int out_size) {
    const float* input = (const float*)d_in[0];
    const float* cond  = (const float*)d_in[1];
    const float* cw    = (const float*)d_in[2];
    const float* cb    = (const float*)d_in[3];
    float* out = (float*)d_out;

    int prep = H * 2 * NKS * 2 * 32;   // 36864
    mml_prep_k<<<(prep + 255) / 256, 256>>>(cw, cb);

    cudaFuncSetAttribute(mml_k, cudaFuncAttributeMaxDynamicSharedMemorySize, SM_TOTAL);
    dim3 grid(Bn / 128, H);            // (256, 8)
    mml_k<<<grid, 256, SM_TOTAL>>>(input, cond, out);
}

// round 8
// speedup vs baseline: 2.6482x; 1.1473x over previous
#include <cuda_runtime.h>
#include <cuda_fp16.h>
#include <cstdint>

#define H    8
#define Bn   32768
#define OF   32
#define NKS  36            // ksteps of 16 -> K = 576
#define KSC  4             // ksteps per chunk
#define NCH  9             // chunks (64 k each)

// W fragments (single fp16 plane), packed for LDG.128:
// uint4 idx = ((h*NKS+ks)*2+ntp)*32+lane
__device__ uint4 g_wf4[H * NKS * 2 * 32];

// smem: 2 P buffers (each: hi plane + lo plane) + cond
#define PROW   144                     // 64k*2B + 16 pad (36-word stride: conflict-free)
#define PSPLIT (128 * PROW)            // 18432
#define PBUF   (2 * PSPLIT)            // 36864
#define SM_CS  (2 * PBUF)              // 73728
#define CSTR   129
#define SM_TOTAL (SM_CS + 32 * CSTR * 4)   // 90240

static __device__ __forceinline__ uint32_t smem_u32(const void* p) {
    uint32_t a;
    asm("{ .reg .u64 t; cvta.to.shared.u64 t, %1; cvt.u32.u64 %0, t; }" : "=r"(a) : "l"(p));
    return a;
}
// fp16 split: hi = rn16(p0,p1); lo = rn16(p - hi)
static __device__ __forceinline__ void split2(float p0, float p1, uint32_t& hi, uint32_t& lo) {
    __half2 h = __floats2half2_rn(p0, p1);
    float2 hf = __half22float2(h);
    __half2 l = __floats2half2_rn(p0 - hf.x, p1 - hf.y);
    hi = *reinterpret_cast<uint32_t*>(&h);
    lo = *reinterpret_cast<uint32_t*>(&l);
}
static __device__ __forceinline__ void gen_ch(float cv, const float* xr, char* hd, char* ld) {
    uint32_t hi[8], lo[8];
#pragma unroll
    for (int j = 0; j < 8; j++) split2(cv * xr[2 * j], cv * xr[2 * j + 1], hi[j], lo[j]);
    reinterpret_cast<uint4*>(hd)[0] = make_uint4(hi[0], hi[1], hi[2], hi[3]);
    reinterpret_cast<uint4*>(hd)[1] = make_uint4(hi[4], hi[5], hi[6], hi[7]);
    reinterpret_cast<uint4*>(ld)[0] = make_uint4(lo[0], lo[1], lo[2], lo[3]);
    reinterpret_cast<uint4*>(ld)[1] = make_uint4(lo[4], lo[5], lo[6], lo[7]);
}
static __device__ __forceinline__ void ldsm_x4(uint32_t a[4], uint32_t addr) {
    asm volatile("ldmatrix.sync.aligned.m8n8.x4.shared.b16 {%0,%1,%2,%3}, [%4];"
                 : "=r"(a[0]), "=r"(a[1]), "=r"(a[2]), "=r"(a[3]) : "r"(addr));
}
static __device__ __forceinline__ void mma_f16(float d[4], const uint32_t a[4],
                                               uint32_t b0, uint32_t b1) {
    asm volatile(
        "mma.sync.aligned.m16n8k16.row.col.f32.f16.f16.f32 "
        "{%0,%1,%2,%3}, {%4,%5,%6,%7}, {%8,%9}, {%0,%1,%2,%3};"
        : "+f"(d[0]), "+f"(d[1]), "+f"(d[2]), "+f"(d[3])
        : "r"(a[0]), "r"(a[1]), "r"(a[2]), "r"(a[3]), "r"(b0), "r"(b1));
}

// permuted W': kp<512: W[o*17+(kp&15)][ch=kp>>4]; 512+i: bias(i); 528+q: W[o*17+16][q];
//              560: bias(16); else 0
static __device__ __forceinline__ float wval(const float* cw, const float* cb,
                                             int h, int kp, int o) {
    if (kp < 512) { int ch = kp >> 4, i = kp & 15; return cw[(h * 544 + o * 17 + i) * 32 + ch]; }
    if (kp < 528) return cb[h * 544 + o * 17 + (kp - 512)];
    if (kp < 560) return cw[(h * 544 + o * 17 + 16) * 32 + (kp - 528)];
    if (kp == 560) return cb[h * 544 + o * 17 + 16];
    return 0.0f;
}
__global__ void mml_prep_k(const float* __restrict__ cw, const float* __restrict__ cb) {
    int idx = blockIdx.x * blockDim.x + threadIdx.x;
    if (idx >= H * NKS * 2 * 32) return;
    int lane = idx & 31;
    int ntp  = (idx >> 5) & 1;
    int ks   = (idx >> 6) % NKS;
    int h    = (idx >> 6) / NKS;
    int g = lane >> 2, t = lane & 3;
    uint32_t v[4];
#pragma unroll
    for (int p = 0; p < 2; p++) {
        int o = (ntp * 2 + p) * 8 + g;
#pragma unroll
        for (int j = 0; j < 2; j++) {
            int k0 = ks * 16 + 2 * t + 8 * j;
            __half2 hv = __floats2half2_rn(wval(cw, cb, h, k0, o), wval(cw, cb, h, k0 + 1, o));
            v[p * 2 + j] = *reinterpret_cast<uint32_t*>(&hv);
        }
    }
    g_wf4[idx] = make_uint4(v[0], v[1], v[2], v[3]);
}

__global__ void __launch_bounds__(256, 2)
mml_k(const float* __restrict__ input, const float* __restrict__ cond,
      float* __restrict__ out) {
    extern __shared__ char smem[];
    const uint32_t sbp = smem_u32(smem);
    const int tid = threadIdx.x;
    const int wid = tid >> 5;
    const int lane = tid & 31;
    const int h = blockIdx.y;
    const size_t sbase = (size_t)(h * Bn + blockIdx.x * 128);

    // cond -> cs[ch][m] (stride 129, conflict-free both ways)
    float* cs = reinterpret_cast<float*>(smem + SM_CS);
    {
        const float* cg = cond + sbase * 32;
#pragma unroll 1
        for (int t = tid; t < 128 * 32; t += 256) cs[(t & 31) * CSTR + (t >> 5)] = cg[t];
    }
    // per-thread x registers (sample m)
    const int m = tid & 127;
    const int hf = tid >> 7;
    float xr[16];
    {
        const float4* xg = reinterpret_cast<const float4*>(input + (sbase + m) * 16);
#pragma unroll
        for (int q = 0; q < 4; q++) {
            float4 v = xg[q];
            xr[q * 4] = v.x; xr[q * 4 + 1] = v.y; xr[q * 4 + 2] = v.z; xr[q * 4 + 3] = v.w;
        }
    }
    __syncthreads();

    float dm[4][4], dc[4][4];
#pragma unroll
    for (int n = 0; n < 4; n++)
#pragma unroll
        for (int e = 0; e < 4; e++) { dm[n][e] = 0.0f; dc[n][e] = 0.0f; }

    // consumer addressing
    const int m0 = wid * 16;
    const int mat = lane >> 3, rin = lane & 7;
    const uint32_t a_off = (uint32_t)((m0 + rin + (mat & 1) * 8) * PROW + (mat >> 1) * 16);
    const uint4* wH = g_wf4 + (size_t)h * NKS * 2 * 32 + lane;
    const float* csm = cs + m;
    char* genb = smem + m * PROW + hf * 64;   // this thread's gen slot (buffer 0)

    // gen chunk c (4 channels / 64 k) into hi-plane base ph
    auto gen_chunk = [&](int c, char* ph) {
        char* pl = ph + PSPLIT;
        if (c < 8) {
            const int ch0 = c * 4 + hf * 2;
            gen_ch(csm[ch0 * CSTR], xr, ph, pl);
            gen_ch(csm[(ch0 + 1) * CSTR], xr, ph + 32, pl + 32);
        } else if (hf == 0) {
            gen_ch(1.0f, xr, ph, pl);                    // kp 512..527: P = x[i]
            uint32_t hi[8], lo[8];
#pragma unroll
            for (int j = 0; j < 8; j++)
                split2(csm[(2 * j) * CSTR], csm[(2 * j + 1) * CSTR], hi[j], lo[j]);
            reinterpret_cast<uint4*>(ph + 32)[0] = make_uint4(hi[0], hi[1], hi[2], hi[3]);
            reinterpret_cast<uint4*>(ph + 32)[1] = make_uint4(hi[4], hi[5], hi[6], hi[7]);
            reinterpret_cast<uint4*>(pl + 32)[0] = make_uint4(lo[0], lo[1], lo[2], lo[3]);
            reinterpret_cast<uint4*>(pl + 32)[1] = make_uint4(lo[4], lo[5], lo[6], lo[7]);
        } else {
            uint32_t hi[8], lo[8];
#pragma unroll
            for (int j = 0; j < 8; j++)
                split2(csm[(16 + 2 * j) * CSTR], csm[(17 + 2 * j) * CSTR], hi[j], lo[j]);
            reinterpret_cast<uint4*>(ph)[0] = make_uint4(hi[0], hi[1], hi[2], hi[3]);
            reinterpret_cast<uint4*>(ph)[1] = make_uint4(hi[4], hi[5], hi[6], hi[7]);
            reinterpret_cast<uint4*>(pl)[0] = make_uint4(lo[0], lo[1], lo[2], lo[3]);
            reinterpret_cast<uint4*>(pl)[1] = make_uint4(lo[4], lo[5], lo[6], lo[7]);
            reinterpret_cast<uint4*>(ph + 32)[0] = make_uint4(0x3C00u, 0, 0, 0);  // kp560 = 1.0 (f16)
            reinterpret_cast<uint4*>(ph + 32)[1] = make_uint4(0, 0, 0, 0);
            reinterpret_cast<uint4*>(pl + 32)[0] = make_uint4(0, 0, 0, 0);
            reinterpret_cast<uint4*>(pl + 32)[1] = make_uint4(0, 0, 0, 0);
        }
    };

    gen_chunk(0, genb);
    __syncthreads();

#pragma unroll 1
    for (int c = 0; c < NCH; c++) {
        // produce next chunk into the other buffer (overlaps with HMMA below)
        if (c + 1 < NCH) gen_chunk(c + 1, genb + ((c + 1) & 1) * PBUF);

        // consume chunk c from buffer c&1
        const uint32_t ph_addr = sbp + (uint32_t)((c & 1) * PBUF) + a_off;
#pragma unroll
        for (int ks = 0; ks < KSC; ks++) {
            const int ksg = c * KSC + ks;
            uint32_t ah[4], al[4];
            ldsm_x4(ah, ph_addr + (uint32_t)(ks * 32));
            ldsm_x4(al, ph_addr + (uint32_t)(PSPLIT + ks * 32));
            uint4 whA = wH[(ksg * 2 + 0) * 32];
            uint4 whB = wH[(ksg * 2 + 1) * 32];
            mma_f16(dm[0], ah, whA.x, whA.y);
            mma_f16(dm[1], ah, whA.z, whA.w);
            mma_f16(dm[2], ah, whB.x, whB.y);
            mma_f16(dm[3], ah, whB.z, whB.w);
            mma_f16(dc[0], al, whA.x, whA.y);
            mma_f16(dc[1], al, whA.z, whA.w);
            mma_f16(dc[2], al, whB.x, whB.y);
            mma_f16(dc[3], al, whB.z, whB.w);
        }
        __syncthreads();
    }

    // ---- epilogue ----
    {
        const int g = lane >> 2, t4 = lane & 3;
#pragma unroll
        for (int nt = 0; nt < 4; nt++) {
            int col = nt * 8 + 2 * t4;
            float2 v0 = make_float2(dm[nt][0] + dc[nt][0], dm[nt][1] + dc[nt][1]);
            float2 v1 = make_float2(dm[nt][2] + dc[nt][2], dm[nt][3] + dc[nt][3]);
            *reinterpret_cast<float2*>(out + (sbase + m0 + g) * OF + col) = v0;
            *reinterpret_cast<float2*>(out + (sbase + m0 + g + 8) * OF + col) = v1;
        }
    }
}

extern "C" void kernel_launch(void* const* d_in, const int* in_sizes, int n_in,
                              void* d_out, int out_size) {
    const float* input = (const float*)d_in[0];
    const float* cond  = (const float*)d_in[1];
    const float* cw    = (const float*)d_in[2];
    const float* cb    = (const float*)d_in[3];
    float* out = (float*)d_out;

    int prep = H * NKS * 2 * 32;   // 18432
    mml_prep_k<<<(prep + 255) / 256, 256>>>(cw, cb);

    cudaFuncSetAttribute(mml_k, cudaFuncAttributeMaxDynamicSharedMemorySize, SM_TOTAL);
    dim3 grid(Bn / 128, H);        // (256, 8)
    mml_k<<<grid, 256, SM_TOTAL>>>(input, cond, out);
}

// round 9
// speedup vs baseline: 2.6609x; 1.0048x over previous
#include <cuda_runtime.h>
#include <cuda_fp16.h>
#include <cstdint>

#define H    8
#define Bn   32768
#define OF   32
#define NKS  36            // ksteps of 16 -> K = 576
#define KSC  4             // ksteps per chunk
#define NCH  9             // chunks (64 k each)
#define MT   64            // samples per CTA
#define NT   128           // threads per CTA

// W fragments (single fp16 plane), packed for LDG.128:
// uint4 idx = ((h*NKS+ks)*2+ntp)*32+lane
__device__ uint4 g_wf4[H * NKS * 2 * 32];

// smem: 2 P buffers (each: hi plane + lo plane) + cond
#define PROW   144                     // 64k*2B + 16 pad (36-word stride: conflict-free)
#define PSPLIT (MT * PROW)             // 9216
#define PBUF   (2 * PSPLIT)            // 18432
#define SM_CS  (2 * PBUF)              // 36864
#define CSTR   65
#define SM_TOTAL (SM_CS + 32 * CSTR * 4)   // 45184

static __device__ __forceinline__ uint32_t smem_u32(const void* p) {
    uint32_t a;
    asm("{ .reg .u64 t; cvta.to.shared.u64 t, %1; cvt.u32.u64 %0, t; }" : "=r"(a) : "l"(p));
    return a;
}
// fp16 split: hi = rn16(p0,p1); lo = rn16(p - hi)
static __device__ __forceinline__ void split2(float p0, float p1, uint32_t& hi, uint32_t& lo) {
    __half2 h = __floats2half2_rn(p0, p1);
    float2 hf = __half22float2(h);
    __half2 l = __floats2half2_rn(p0 - hf.x, p1 - hf.y);
    hi = *reinterpret_cast<uint32_t*>(&h);
    lo = *reinterpret_cast<uint32_t*>(&l);
}
static __device__ __forceinline__ void gen_ch(float cv, const float* xr, char* hd, char* ld) {
    uint32_t hi[8], lo[8];
#pragma unroll
    for (int j = 0; j < 8; j++) split2(cv * xr[2 * j], cv * xr[2 * j + 1], hi[j], lo[j]);
    reinterpret_cast<uint4*>(hd)[0] = make_uint4(hi[0], hi[1], hi[2], hi[3]);
    reinterpret_cast<uint4*>(hd)[1] = make_uint4(hi[4], hi[5], hi[6], hi[7]);
    reinterpret_cast<uint4*>(ld)[0] = make_uint4(lo[0], lo[1], lo[2], lo[3]);
    reinterpret_cast<uint4*>(ld)[1] = make_uint4(lo[4], lo[5], lo[6], lo[7]);
}
static __device__ __forceinline__ void ldsm_x4(uint32_t a[4], uint32_t addr) {
    asm volatile("ldmatrix.sync.aligned.m8n8.x4.shared.b16 {%0,%1,%2,%3}, [%4];"
                 : "=r"(a[0]), "=r"(a[1]), "=r"(a[2]), "=r"(a[3]) : "r"(addr));
}
static __device__ __forceinline__ void mma_f16(float d[4], const uint32_t a[4],
                                               uint32_t b0, uint32_t b1) {
    asm volatile(
        "mma.sync.aligned.m16n8k16.row.col.f32.f16.f16.f32 "
        "{%0,%1,%2,%3}, {%4,%5,%6,%7}, {%8,%9}, {%0,%1,%2,%3};"
        : "+f"(d[0]), "+f"(d[1]), "+f"(d[2]), "+f"(d[3])
        : "r"(a[0]), "r"(a[1]), "r"(a[2]), "r"(a[3]), "r"(b0), "r"(b1));
}

// permuted W': kp<512: W[o*17+(kp&15)][ch=kp>>4]; 512+i: bias(i); 528+q: W[o*17+16][q];
//              560: bias(16); else 0
static __device__ __forceinline__ float wval(const float* cw, const float* cb,
                                             int h, int kp, int o) {
    if (kp < 512) { int ch = kp >> 4, i = kp & 15; return cw[(h * 544 + o * 17 + i) * 32 + ch]; }
    if (kp < 528) return cb[h * 544 + o * 17 + (kp - 512)];
    if (kp < 560) return cw[(h * 544 + o * 17 + 16) * 32 + (kp - 528)];
    if (kp == 560) return cb[h * 544 + o * 17 + 16];
    return 0.0f;
}
__global__ void mml_prep_k(const float* __restrict__ cw, const float* __restrict__ cb) {
    int idx = blockIdx.x * blockDim.x + threadIdx.x;
    if (idx >= H * NKS * 2 * 32) return;
    int lane = idx & 31;
    int ntp  = (idx >> 5) & 1;
    int ks   = (idx >> 6) % NKS;
    int h    = (idx >> 6) / NKS;
    int g = lane >> 2, t = lane & 3;
    uint32_t v[4];
#pragma unroll
    for (int p = 0; p < 2; p++) {
        int o = (ntp * 2 + p) * 8 + g;
#pragma unroll
        for (int j = 0; j < 2; j++) {
            int k0 = ks * 16 + 2 * t + 8 * j;
            __half2 hv = __floats2half2_rn(wval(cw, cb, h, k0, o), wval(cw, cb, h, k0 + 1, o));
            v[p * 2 + j] = *reinterpret_cast<uint32_t*>(&hv);
        }
    }
    g_wf4[idx] = make_uint4(v[0], v[1], v[2], v[3]);
}

__global__ void __launch_bounds__(NT, 3)
mml_k(const float* __restrict__ input, const float* __restrict__ cond,
      float* __restrict__ out) {
    extern __shared__ char smem[];
    const uint32_t sbp = smem_u32(smem);
    const int tid = threadIdx.x;
    const int wid = tid >> 5;
    const int lane = tid & 31;
    const int h = blockIdx.y;
    const size_t sbase = (size_t)(h * Bn + blockIdx.x * MT);

    // cond -> cs[ch][m] (stride 65, conflict-free both ways)
    float* cs = reinterpret_cast<float*>(smem + SM_CS);
    {
        const float* cg = cond + sbase * 32;
#pragma unroll 1
        for (int t = tid; t < MT * 32; t += NT) cs[(t & 31) * CSTR + (t >> 5)] = cg[t];
    }
    // per-thread x registers (sample m; both hf halves hold the same sample's x)
    const int m = tid & (MT - 1);
    const int hf = tid >> 6;
    float xr[16];
    {
        const float4* xg = reinterpret_cast<const float4*>(input + (sbase + m) * 16);
#pragma unroll
        for (int q = 0; q < 4; q++) {
            float4 v = xg[q];
            xr[q * 4] = v.x; xr[q * 4 + 1] = v.y; xr[q * 4 + 2] = v.z; xr[q * 4 + 3] = v.w;
        }
    }
    __syncthreads();

    float dm[4][4], dc[4][4];
#pragma unroll
    for (int n = 0; n < 4; n++)
#pragma unroll
        for (int e = 0; e < 4; e++) { dm[n][e] = 0.0f; dc[n][e] = 0.0f; }

    // consumer addressing (4 warps, 16 rows each)
    const int m0 = wid * 16;
    const int mat = lane >> 3, rin = lane & 7;
    const uint32_t a_off = (uint32_t)((m0 + rin + (mat & 1) * 8) * PROW + (mat >> 1) * 16);
    const uint4* wH = g_wf4 + (size_t)h * NKS * 2 * 32 + lane;
    const float* csm = cs + m;
    char* genb = smem + m * PROW + hf * 64;   // this thread's gen slot (buffer 0)

    // gen chunk c (4 channels / 64 k) into hi-plane base ph
    auto gen_chunk = [&](int c, char* ph) {
        char* pl = ph + PSPLIT;
        if (c < 8) {
            const int ch0 = c * 4 + hf * 2;
            gen_ch(csm[ch0 * CSTR], xr, ph, pl);
            gen_ch(csm[(ch0 + 1) * CSTR], xr, ph + 32, pl + 32);
        } else if (hf == 0) {
            gen_ch(1.0f, xr, ph, pl);                    // kp 512..527: P = x[i]
            uint32_t hi[8], lo[8];
#pragma unroll
            for (int j = 0; j < 8; j++)
                split2(csm[(2 * j) * CSTR], csm[(2 * j + 1) * CSTR], hi[j], lo[j]);
            reinterpret_cast<uint4*>(ph + 32)[0] = make_uint4(hi[0], hi[1], hi[2], hi[3]);
            reinterpret_cast<uint4*>(ph + 32)[1] = make_uint4(hi[4], hi[5], hi[6], hi[7]);
            reinterpret_cast<uint4*>(pl + 32)[0] = make_uint4(lo[0], lo[1], lo[2], lo[3]);
            reinterpret_cast<uint4*>(pl + 32)[1] = make_uint4(lo[4], lo[5], lo[6], lo[7]);
        } else {
            uint32_t hi[8], lo[8];
#pragma unroll
            for (int j = 0; j < 8; j++)
                split2(csm[(16 + 2 * j) * CSTR], csm[(17 + 2 * j) * CSTR], hi[j], lo[j]);
            reinterpret_cast<uint4*>(ph)[0] = make_uint4(hi[0], hi[1], hi[2], hi[3]);
            reinterpret_cast<uint4*>(ph)[1] = make_uint4(hi[4], hi[5], hi[6], hi[7]);
            reinterpret_cast<uint4*>(pl)[0] = make_uint4(lo[0], lo[1], lo[2], lo[3]);
            reinterpret_cast<uint4*>(pl)[1] = make_uint4(lo[4], lo[5], lo[6], lo[7]);
            reinterpret_cast<uint4*>(ph + 32)[0] = make_uint4(0x3C00u, 0, 0, 0);  // kp560 = 1.0 (f16)
            reinterpret_cast<uint4*>(ph + 32)[1] = make_uint4(0, 0, 0, 0);
            reinterpret_cast<uint4*>(pl + 32)[0] = make_uint4(0, 0, 0, 0);
            reinterpret_cast<uint4*>(pl + 32)[1] = make_uint4(0, 0, 0, 0);
        }
    };

    gen_chunk(0, genb);
    __syncthreads();

#pragma unroll 1
    for (int c = 0; c < NCH; c++) {
        // ---- 1. prefetch ALL fragments of chunk c into registers ----
        const uint32_t ph_addr = sbp + (uint32_t)((c & 1) * PBUF) + a_off;
        uint32_t ah[KSC][4], al[KSC][4];
        uint4 wA[KSC], wB[KSC];
#pragma unroll
        for (int ks = 0; ks < KSC; ks++) {
            ldsm_x4(ah[ks], ph_addr + (uint32_t)(ks * 32));
            ldsm_x4(al[ks], ph_addr + (uint32_t)(PSPLIT + ks * 32));
            const int ksg = c * KSC + ks;
            wA[ks] = wH[(ksg * 2 + 0) * 32];
            wB[ks] = wH[(ksg * 2 + 1) * 32];
        }

        // ---- 2. gen next chunk (long independent stream hides load latency) ----
        if (c + 1 < NCH) gen_chunk(c + 1, genb + ((c + 1) & 1) * PBUF);

        // ---- 3. HMMA from registers ----
#pragma unroll
        for (int ks = 0; ks < KSC; ks++) {
            mma_f16(dm[0], ah[ks], wA[ks].x, wA[ks].y);
            mma_f16(dm[1], ah[ks], wA[ks].z, wA[ks].w);
            mma_f16(dm[2], ah[ks], wB[ks].x, wB[ks].y);
            mma_f16(dm[3], ah[ks], wB[ks].z, wB[ks].w);
            mma_f16(dc[0], al[ks], wA[ks].x, wA[ks].y);
            mma_f16(dc[1], al[ks], wA[ks].z, wA[ks].w);
            mma_f16(dc[2], al[ks], wB[ks].x, wB[ks].y);
            mma_f16(dc[3], al[ks], wB[ks].z, wB[ks].w);
        }
        __syncthreads();
    }

    // ---- epilogue ----
    {
        const int g = lane >> 2, t4 = lane & 3;
#pragma unroll
        for (int nt = 0; nt < 4; nt++) {
            int col = nt * 8 + 2 * t4;
            float2 v0 = make_float2(dm[nt][0] + dc[nt][0], dm[nt][1] + dc[nt][1]);
            float2 v1 = make_float2(dm[nt][2] + dc[nt][2], dm[nt][3] + dc[nt][3]);
            *reinterpret_cast<float2*>(out + (sbase + m0 + g) * OF + col) = v0;
            *reinterpret_cast<float2*>(out + (sbase + m0 + g + 8) * OF + col) = v1;
        }
    }
}

extern "C" void kernel_launch(void* const* d_in, const int* in_sizes, int n_in,
                              void* d_out, int out_size) {
    const float* input = (const float*)d_in[0];
    const float* cond  = (const float*)d_in[1];
    const float* cw    = (const float*)d_in[2];
    const float* cb    = (const float*)d_in[3];
    float* out = (float*)d_out;

    int prep = H * NKS * 2 * 32;   // 18432
    mml_prep_k<<<(prep + 255) / 256, 256>>>(cw, cb);

    cudaFuncSetAttribute(mml_k, cudaFuncAttributeMaxDynamicSharedMemorySize, SM_TOTAL);
    dim3 grid(Bn / MT, H);         // (512, 8)
    mml_k<<<grid, NT, SM_TOTAL>>>(input, cond, out);
}

// round 10
// speedup vs baseline: 3.8553x; 1.4489x over previous
#include <cuda_runtime.h>
#include <cuda_fp16.h>
#include <cstdint>

#define H    8
#define Bn   32768
#define OF   32
#define NKS  36            // ksteps of 16 -> K = 576
#define KSC  4             // ksteps per chunk
#define NCH  9             // chunks (64 k each)
#define MT   64            // samples per CTA
#define NT   128           // threads per CTA (4 warps, 16 samples/warp)

// W fragments (single fp16 plane), packed for LDG.128:
// uint4 idx = ((h*NKS+ks)*2+ntp)*32+lane
__device__ uint4 g_wf4[H * NKS * 2 * 32];

// smem: single P buffer (hi+lo planes) + per-warp cond
#define PROW   144                     // 64k*2B + 16 pad (36-word stride: conflict-free)
#define PSPLIT (MT * PROW)             // 9216
#define SM_CS  (2 * PSPLIT)            // 18432
#define CSTR   17                      // cond stride within a warp region (coprime w/ 32)
#define CWARP  (32 * CSTR * 4)         // 2176 bytes per warp
#define SM_TOTAL (SM_CS + 4 * CWARP)   // 27136

static __device__ __forceinline__ uint32_t smem_u32(const void* p) {
    uint32_t a;
    asm("{ .reg .u64 t; cvta.to.shared.u64 t, %1; cvt.u32.u64 %0, t; }" : "=r"(a) : "l"(p));
    return a;
}
// fp16 split: hi = rn16(p0,p1); lo = rn16(p - hi)
static __device__ __forceinline__ void split2(float p0, float p1, uint32_t& hi, uint32_t& lo) {
    __half2 h = __floats2half2_rn(p0, p1);
    float2 hf = __half22float2(h);
    __half2 l = __floats2half2_rn(p0 - hf.x, p1 - hf.y);
    hi = *reinterpret_cast<uint32_t*>(&h);
    lo = *reinterpret_cast<uint32_t*>(&l);
}
static __device__ __forceinline__ void gen_ch(float cv, const float* xr, char* hd, char* ld) {
    uint32_t hi[8], lo[8];
#pragma unroll
    for (int j = 0; j < 8; j++) split2(cv * xr[2 * j], cv * xr[2 * j + 1], hi[j], lo[j]);
    reinterpret_cast<uint4*>(hd)[0] = make_uint4(hi[0], hi[1], hi[2], hi[3]);
    reinterpret_cast<uint4*>(hd)[1] = make_uint4(hi[4], hi[5], hi[6], hi[7]);
    reinterpret_cast<uint4*>(ld)[0] = make_uint4(lo[0], lo[1], lo[2], lo[3]);
    reinterpret_cast<uint4*>(ld)[1] = make_uint4(lo[4], lo[5], lo[6], lo[7]);
}
static __device__ __forceinline__ void ldsm_x4(uint32_t a[4], uint32_t addr) {
    asm volatile("ldmatrix.sync.aligned.m8n8.x4.shared.b16 {%0,%1,%2,%3}, [%4];"
                 : "=r"(a[0]), "=r"(a[1]), "=r"(a[2]), "=r"(a[3]) : "r"(addr));
}
static __device__ __forceinline__ void mma_f16(float d[4], const uint32_t a[4],
                                               uint32_t b0, uint32_t b1) {
    asm volatile(
        "mma.sync.aligned.m16n8k16.row.col.f32.f16.f16.f32 "
        "{%0,%1,%2,%3}, {%4,%5,%6,%7}, {%8,%9}, {%0,%1,%2,%3};"
        : "+f"(d[0]), "+f"(d[1]), "+f"(d[2]), "+f"(d[3])
        : "r"(a[0]), "r"(a[1]), "r"(a[2]), "r"(a[3]), "r"(b0), "r"(b1));
}

// permuted W': kp<512: W[o*17+(kp&15)][ch=kp>>4]; 512+i: bias(i); 528+q: W[o*17+16][q];
//              560: bias(16); else 0
static __device__ __forceinline__ float wval(const float* cw, const float* cb,
                                             int h, int kp, int o) {
    if (kp < 512) { int ch = kp >> 4, i = kp & 15; return cw[(h * 544 + o * 17 + i) * 32 + ch]; }
    if (kp < 528) return cb[h * 544 + o * 17 + (kp - 512)];
    if (kp < 560) return cw[(h * 544 + o * 17 + 16) * 32 + (kp - 528)];
    if (kp == 560) return cb[h * 544 + o * 17 + 16];
    return 0.0f;
}
__global__ void mml_prep_k(const float* __restrict__ cw, const float* __restrict__ cb) {
    int idx = blockIdx.x * blockDim.x + threadIdx.x;
    if (idx >= H * NKS * 2 * 32) return;
    int lane = idx & 31;
    int ntp  = (idx >> 5) & 1;
    int ks   = (idx >> 6) % NKS;
    int h    = (idx >> 6) / NKS;
    int g = lane >> 2, t = lane & 3;
    uint32_t v[4];
#pragma unroll
    for (int p = 0; p < 2; p++) {
        int o = (ntp * 2 + p) * 8 + g;
#pragma unroll
        for (int j = 0; j < 2; j++) {
            int k0 = ks * 16 + 2 * t + 8 * j;
            __half2 hv = __floats2half2_rn(wval(cw, cb, h, k0, o), wval(cw, cb, h, k0 + 1, o));
            v[p * 2 + j] = *reinterpret_cast<uint32_t*>(&hv);
        }
    }
    g_wf4[idx] = make_uint4(v[0], v[1], v[2], v[3]);
}

__global__ void __launch_bounds__(NT, 5)
mml_k(const float* __restrict__ input, const float* __restrict__ cond,
      float* __restrict__ out) {
    extern __shared__ char smem[];
    const uint32_t sbp = smem_u32(smem);
    const int tid = threadIdx.x;
    const int wid = tid >> 5;
    const int lane = tid & 31;
    const int h = blockIdx.y;
    const size_t sbase = (size_t)(h * Bn + blockIdx.x * MT);

    // ---- warp-local prologue: cond for this warp's 16 samples ----
    // csw[ch*17 + s] = cond[sample m0w+s][ch]; write pattern conflict-free (17 coprime 32)
    float* csw = reinterpret_cast<float*>(smem + SM_CS + wid * CWARP);
    {
        const float* cg = cond + (sbase + wid * 16) * 32;
#pragma unroll
        for (int i = 0; i < 16; i++) csw[lane * CSTR + i] = cg[i * 32 + lane];
    }

    // thread roles: sample s within warp, half hf of each 64-k chunk
    const int s = lane & 15;
    const int hf = lane >> 4;
    const int m = wid * 16 + s;              // CTA-wide row
    float xr[16];
    {
        const float4* xg = reinterpret_cast<const float4*>(input + (sbase + m) * 16);
#pragma unroll
        for (int q = 0; q < 4; q++) {
            float4 v = xg[q];
            xr[q * 4] = v.x; xr[q * 4 + 1] = v.y; xr[q * 4 + 2] = v.z; xr[q * 4 + 3] = v.w;
        }
    }
    __syncwarp();

    float dm[4][4], dc[4][4];
#pragma unroll
    for (int n = 0; n < 4; n++)
#pragma unroll
        for (int e = 0; e < 4; e++) { dm[n][e] = 0.0f; dc[n][e] = 0.0f; }

    // consumer addressing (warp reads only its own 16 rows)
    const int m0 = wid * 16;
    const int mat = lane >> 3, rin = lane & 7;
    const uint32_t a_off = (uint32_t)((m0 + rin + (mat & 1) * 8) * PROW + (mat >> 1) * 16);
    const uint32_t ph_base = sbp + a_off;
    const uint4* wH = g_wf4 + (size_t)h * NKS * 2 * 32 + lane;
    const float* csm = csw + s;
    char* genb = smem + m * PROW + hf * 64;  // this thread's half-row slot

#pragma unroll 1
    for (int c = 0; c < NCH; c++) {
        // ---- gen chunk c (this warp's 16 rows only) ----
        {
            char* ph = genb;
            char* pl = ph + PSPLIT;
            if (c < 8) {
                const int ch0 = c * 4 + hf * 2;
                gen_ch(csm[ch0 * CSTR], xr, ph, pl);
                gen_ch(csm[(ch0 + 1) * CSTR], xr, ph + 32, pl + 32);
            } else if (hf == 0) {
                gen_ch(1.0f, xr, ph, pl);                // kp 512..527: P = x[i]
                uint32_t hi[8], lo[8];
#pragma unroll
                for (int j = 0; j < 8; j++)
                    split2(csm[(2 * j) * CSTR], csm[(2 * j + 1) * CSTR], hi[j], lo[j]);
                reinterpret_cast<uint4*>(ph + 32)[0] = make_uint4(hi[0], hi[1], hi[2], hi[3]);
                reinterpret_cast<uint4*>(ph + 32)[1] = make_uint4(hi[4], hi[5], hi[6], hi[7]);
                reinterpret_cast<uint4*>(pl + 32)[0] = make_uint4(lo[0], lo[1], lo[2], lo[3]);
                reinterpret_cast<uint4*>(pl + 32)[1] = make_uint4(lo[4], lo[5], lo[6], lo[7]);
            } else {
                uint32_t hi[8], lo[8];
#pragma unroll
                for (int j = 0; j < 8; j++)
                    split2(csm[(16 + 2 * j) * CSTR], csm[(17 + 2 * j) * CSTR], hi[j], lo[j]);
                reinterpret_cast<uint4*>(ph)[0] = make_uint4(hi[0], hi[1], hi[2], hi[3]);
                reinterpret_cast<uint4*>(ph)[1] = make_uint4(hi[4], hi[5], hi[6], hi[7]);
                reinterpret_cast<uint4*>(pl)[0] = make_uint4(lo[0], lo[1], lo[2], lo[3]);
                reinterpret_cast<uint4*>(pl)[1] = make_uint4(lo[4], lo[5], lo[6], lo[7]);
                reinterpret_cast<uint4*>(ph + 32)[0] = make_uint4(0x3C00u, 0, 0, 0);  // kp560 = 1.0
                reinterpret_cast<uint4*>(ph + 32)[1] = make_uint4(0, 0, 0, 0);
                reinterpret_cast<uint4*>(pl + 32)[0] = make_uint4(0, 0, 0, 0);
                reinterpret_cast<uint4*>(pl + 32)[1] = make_uint4(0, 0, 0, 0);
            }
        }
        __syncwarp();   // cross-lane STS -> LDSM visibility (warp-scope, cheap)

        // ---- consume: 4 ksteps from this warp's rows ----
#pragma unroll
        for (int ks = 0; ks < KSC; ks++) {
            const int ksg = c * KSC + ks;
            uint32_t ah[4], al[4];
            ldsm_x4(ah, ph_base + (uint32_t)(ks * 32));
            ldsm_x4(al, ph_base + (uint32_t)(PSPLIT + ks * 32));
            uint4 whA = wH[(ksg * 2 + 0) * 32];
            uint4 whB = wH[(ksg * 2 + 1) * 32];
            mma_f16(dm[0], ah, whA.x, whA.y);
            mma_f16(dm[1], ah, whA.z, whA.w);
            mma_f16(dm[2], ah, whB.x, whB.y);
            mma_f16(dm[3], ah, whB.z, whB.w);
            mma_f16(dc[0], al, whA.x, whA.y);
            mma_f16(dc[1], al, whA.z, whA.w);
            mma_f16(dc[2], al, whB.x, whB.y);
            mma_f16(dc[3], al, whB.z, whB.w);
        }
        // no sync needed before next gen: warp-private rows; in-order issue +
        // register scoreboard guarantee LDSM completed before next STS issues
    }

    // ---- epilogue ----
    {
        const int g = lane >> 2, t4 = lane & 3;
#pragma unroll
        for (int nt = 0; nt < 4; nt++) {
            int col = nt * 8 + 2 * t4;
            float2 v0 = make_float2(dm[nt][0] + dc[nt][0], dm[nt][1] + dc[nt][1]);
            float2 v1 = make_float2(dm[nt][2] + dc[nt][2], dm[nt][3] + dc[nt][3]);
            *reinterpret_cast<float2*>(out + (sbase + m0 + g) * OF + col) = v0;
            *reinterpret_cast<float2*>(out + (sbase + m0 + g + 8) * OF + col) = v1;
        }
    }
}

extern "C" void kernel_launch(void* const* d_in, const int* in_sizes, int n_in,
                              void* d_out, int out_size) {
    const float* input = (const float*)d_in[0];
    const float* cond  = (const float*)d_in[1];
    const float* cw    = (const float*)d_in[2];
    const float* cb    = (const float*)d_in[3];
    float* out = (float*)d_out;

    int prep = H * NKS * 2 * 32;   // 18432
    mml_prep_k<<<(prep + 255) / 256, 256>>>(cw, cb);

    cudaFuncSetAttribute(mml_k, cudaFuncAttributeMaxDynamicSharedMemorySize, SM_TOTAL);
    dim3 grid(Bn / MT, H);         // (512, 8)
    mml_k<<<grid, NT, SM_TOTAL>>>(input, cond, out);
}

// round 11
// speedup vs baseline: 4.6271x; 1.2002x over previous
#include <cuda_runtime.h>
#include <cuda_fp16.h>
#include <cstdint>

#define H    8
#define Bn   32768
#define OF   32
#define NKS  36            // ksteps of 16 -> K = 576
#define MT   64            // samples per CTA
#define NT   128           // threads per CTA (4 warps, 16 samples/warp)

// W fragments (single fp16 plane), packed for LDG.128:
// uint4 idx = ((h*NKS+ks)*2+ntp)*32+lane
__device__ uint4 g_wf4[H * NKS * 2 * 32];

// smem: per-warp cond + x transposes only (no P buffer at all)
// per-warp block: csw[ch*17+s] (544 f) then xsw[i*17+s] (272 f) = 816 floats
#define WBLK  816
#define SM_TOTAL (4 * WBLK * 4)        // 13056 bytes

// fp16 split: hi = rn16(p0,p1); lo = rn16(p - hi)
static __device__ __forceinline__ void split2(float p0, float p1, uint32_t& hi, uint32_t& lo) {
    __half2 h = __floats2half2_rn(p0, p1);
    float2 hf = __half22float2(h);
    __half2 l = __floats2half2_rn(p0 - hf.x, p1 - hf.y);
    hi = *reinterpret_cast<uint32_t*>(&h);
    lo = *reinterpret_cast<uint32_t*>(&l);
}
static __device__ __forceinline__ void mma_f16(float d[4], const uint32_t a[4],
                                               uint32_t b0, uint32_t b1) {
    asm volatile(
        "mma.sync.aligned.m16n8k16.row.col.f32.f16.f16.f32 "
        "{%0,%1,%2,%3}, {%4,%5,%6,%7}, {%8,%9}, {%0,%1,%2,%3};"
        : "+f"(d[0]), "+f"(d[1]), "+f"(d[2]), "+f"(d[3])
        : "r"(a[0]), "r"(a[1]), "r"(a[2]), "r"(a[3]), "r"(b0), "r"(b1));
}

// permuted W': kp<512: W[o*17+(kp&15)][ch=kp>>4]; 512+i: bias(i); 528+q: W[o*17+16][q];
//              560: bias(16); else 0
static __device__ __forceinline__ float wval(const float* cw, const float* cb,
                                             int h, int kp, int o) {
    if (kp < 512) { int ch = kp >> 4, i = kp & 15; return cw[(h * 544 + o * 17 + i) * 32 + ch]; }
    if (kp < 528) return cb[h * 544 + o * 17 + (kp - 512)];
    if (kp < 560) return cw[(h * 544 + o * 17 + 16) * 32 + (kp - 528)];
    if (kp == 560) return cb[h * 544 + o * 17 + 16];
    return 0.0f;
}
__global__ void mml_prep_k(const float* __restrict__ cw, const float* __restrict__ cb) {
    int idx = blockIdx.x * blockDim.x + threadIdx.x;
    if (idx >= H * NKS * 2 * 32) return;
    int lane = idx & 31;
    int ntp  = (idx >> 5) & 1;
    int ks   = (idx >> 6) % NKS;
    int h    = (idx >> 6) / NKS;
    int g = lane >> 2, t = lane & 3;
    uint32_t v[4];
#pragma unroll
    for (int p = 0; p < 2; p++) {
        int o = (ntp * 2 + p) * 8 + g;
#pragma unroll
        for (int j = 0; j < 2; j++) {
            int k0 = ks * 16 + 2 * t + 8 * j;
            __half2 hv = __floats2half2_rn(wval(cw, cb, h, k0, o), wval(cw, cb, h, k0 + 1, o));
            v[p * 2 + j] = *reinterpret_cast<uint32_t*>(&hv);
        }
    }
    g_wf4[idx] = make_uint4(v[0], v[1], v[2], v[3]);
}

__global__ void __launch_bounds__(NT, 5)
mml_k(const float* __restrict__ input, const float* __restrict__ cond,
      float* __restrict__ out) {
    extern __shared__ float smf[];
    const int tid = threadIdx.x;
    const int wid = tid >> 5;
    const int lane = tid & 31;
    const int h = blockIdx.y;
    const size_t sbase = (size_t)(h * Bn + blockIdx.x * MT);

    float* csw = smf + wid * WBLK;        // [ch*17 + s], ch 0..31
    float* xsw = csw + 544;               // [i*17 + s],  i 0..15

    // ---- warp-local staging (one-time) ----
    {
        const float* cg = cond + (sbase + wid * 16) * 32;
#pragma unroll
        for (int i = 0; i < 16; i++) csw[lane * 17 + i] = cg[i * 32 + lane];
        if (lane < 16) {
            const float4* xg = reinterpret_cast<const float4*>(input + (sbase + wid * 16 + lane) * 16);
#pragma unroll
            for (int q = 0; q < 4; q++) {
                float4 v = xg[q];
                xsw[(q * 4 + 0) * 17 + lane] = v.x;
                xsw[(q * 4 + 1) * 17 + lane] = v.y;
                xsw[(q * 4 + 2) * 17 + lane] = v.z;
                xsw[(q * 4 + 3) * 17 + lane] = v.w;
            }
        }
    }
    __syncwarp();

    // per-lane fixed x values: rows {g, g+8}, cols {2t,2t+1,2t+8,2t+9}
    const int g = lane >> 2, t = lane & 3;
    const int i0 = 2 * t, i1 = 2 * t + 1, i2 = 2 * t + 8, i3 = 2 * t + 9;
    float xg0[4], xg1[4];
    xg0[0] = xsw[i0 * 17 + g];     xg0[1] = xsw[i1 * 17 + g];
    xg0[2] = xsw[i2 * 17 + g];     xg0[3] = xsw[i3 * 17 + g];
    xg1[0] = xsw[i0 * 17 + g + 8]; xg1[1] = xsw[i1 * 17 + g + 8];
    xg1[2] = xsw[i2 * 17 + g + 8]; xg1[3] = xsw[i3 * 17 + g + 8];

    float dm[4][4], dc[4][4];
#pragma unroll
    for (int n = 0; n < 4; n++)
#pragma unroll
        for (int e = 0; e < 4; e++) { dm[n][e] = 0.0f; dc[n][e] = 0.0f; }

    const uint4* wH = g_wf4 + (size_t)h * NKS * 2 * 32 + lane;

    // fragment builder: 8 products -> hi[4], lo[4] (reg order matches mma A frag)
    auto mkfrag = [&](float p00, float p01, float p10, float p11,
                      float p02, float p03, float p12, float p13,
                      uint32_t hi[4], uint32_t lo[4]) {
        split2(p00, p01, hi[0], lo[0]);
        split2(p10, p11, hi[1], lo[1]);
        split2(p02, p03, hi[2], lo[2]);
        split2(p12, p13, hi[3], lo[3]);
    };
    auto do_mmas = [&](const uint32_t hi[4], const uint32_t lo[4], int ks) {
        uint4 whA = wH[(ks * 2 + 0) * 32];
        uint4 whB = wH[(ks * 2 + 1) * 32];
        mma_f16(dm[0], hi, whA.x, whA.y);
        mma_f16(dm[1], hi, whA.z, whA.w);
        mma_f16(dm[2], hi, whB.x, whB.y);
        mma_f16(dm[3], hi, whB.z, whB.w);
        mma_f16(dc[0], lo, whA.x, whA.y);
        mma_f16(dc[1], lo, whA.z, whA.w);
        mma_f16(dc[2], lo, whB.x, whB.y);
        mma_f16(dc[3], lo, whB.z, whB.w);
    };

    // ---- ksteps 0..31: P = cond[ch] * x[i], ch = ks ----
#pragma unroll 1
    for (int c = 0; c < 8; c++) {
#pragma unroll
        for (int u = 0; u < 4; u++) {
            const int ks = c * 4 + u;
            float cv0 = csw[ks * 17 + g];
            float cv1 = csw[ks * 17 + g + 8];
            uint32_t hi[4], lo[4];
            mkfrag(cv0 * xg0[0], cv0 * xg0[1], cv1 * xg1[0], cv1 * xg1[1],
                   cv0 * xg0[2], cv0 * xg0[3], cv1 * xg1[2], cv1 * xg1[3], hi, lo);
            do_mmas(hi, lo, ks);
        }
    }
    // ---- kstep 32: P = x[i] (bias rows, cv = 1) ----
    {
        uint32_t hi[4], lo[4];
        mkfrag(xg0[0], xg0[1], xg1[0], xg1[1], xg0[2], xg0[3], xg1[2], xg1[3], hi, lo);
        do_mmas(hi, lo, 32);
    }
    // ---- ksteps 33,34: P = cond[q] (+16) directly ----
#pragma unroll
    for (int u = 0; u < 2; u++) {
        const int qb = u * 16;
        uint32_t hi[4], lo[4];
        mkfrag(csw[(qb + i0) * 17 + g],     csw[(qb + i1) * 17 + g],
               csw[(qb + i0) * 17 + g + 8], csw[(qb + i1) * 17 + g + 8],
               csw[(qb + i2) * 17 + g],     csw[(qb + i3) * 17 + g],
               csw[(qb + i2) * 17 + g + 8], csw[(qb + i3) * 17 + g + 8], hi, lo);
        do_mmas(hi, lo, 33 + u);
    }
    // ---- kstep 35: P[.,560] = 1.0, rest 0 ----
    {
        uint32_t one = (t == 0) ? 0x00003C00u : 0u;
        uint32_t hi[4] = { one, one, 0u, 0u };
        uint32_t lo[4] = { 0u, 0u, 0u, 0u };
        do_mmas(hi, lo, 35);
    }

    // ---- epilogue ----
    {
        const int m0 = wid * 16;
        const int gg = lane >> 2, t4 = lane & 3;
#pragma unroll
        for (int nt = 0; nt < 4; nt++) {
            int col = nt * 8 + 2 * t4;
            float2 v0 = make_float2(dm[nt][0] + dc[nt][0], dm[nt][1] + dc[nt][1]);
            float2 v1 = make_float2(dm[nt][2] + dc[nt][2], dm[nt][3] + dc[nt][3]);
            *reinterpret_cast<float2*>(out + (sbase + m0 + gg) * OF + col) = v0;
            *reinterpret_cast<float2*>(out + (sbase + m0 + gg + 8) * OF + col) = v1;
        }
    }
}

extern "C" void kernel_launch(void* const* d_in, const int* in_sizes, int n_in,
                              void* d_out, int out_size) {
    const float* input = (const float*)d_in[0];
    const float* cond  = (const float*)d_in[1];
    const float* cw    = (const float*)d_in[2];
    const float* cb    = (const float*)d_in[3];
    float* out = (float*)d_out;

    int prep = H * NKS * 2 * 32;   // 18432
    mml_prep_k<<<(prep + 255) / 256, 256>>>(cw, cb);

    cudaFuncSetAttribute(mml_k, cudaFuncAttributeMaxDynamicSharedMemorySize, SM_TOTAL);
    dim3 grid(Bn / MT, H);         // (512, 8)
    mml_k<<<grid, NT, SM_TOTAL>>>(input, cond, out);
}

// round 12
// speedup vs baseline: 6.2180x; 1.3438x over previous
#include <cuda_runtime.h>
#include <cuda_fp16.h>
#include <cstdint>

#define H    8
#define Bn   32768
#define OF   32
#define NKS  36            // ksteps of 16 -> K = 576
#define MT   128           // samples per CTA
#define NT   128           // 4 warps, 32 samples/warp (2 m16 tiles)

// W fragments (single fp16 plane), packed for LDG.128:
// uint4 idx = ((h*NKS+ks)*2+ntp)*32+lane
__device__ uint4 g_wf4[H * NKS * 2 * 32];

// smem: per-warp cond + x transposes (stride 33, conflict-free)
// per-warp: csw[ch*33+s] (1056 f) then xsw[i*33+s] (528 f) = 1584 floats
#define WBLK  1584
#define SM_TOTAL (4 * WBLK * 4)        // 25344 bytes

static __device__ __forceinline__ uint32_t cvt2(float p0, float p1) {
    __half2 hv = __floats2half2_rn(p0, p1);
    return *reinterpret_cast<uint32_t*>(&hv);
}
static __device__ __forceinline__ void mma_f16(float d[4], const uint32_t a[4],
                                               uint32_t b0, uint32_t b1) {
    asm volatile(
        "mma.sync.aligned.m16n8k16.row.col.f32.f16.f16.f32 "
        "{%0,%1,%2,%3}, {%4,%5,%6,%7}, {%8,%9}, {%0,%1,%2,%3};"
        : "+f"(d[0]), "+f"(d[1]), "+f"(d[2]), "+f"(d[3])
        : "r"(a[0]), "r"(a[1]), "r"(a[2]), "r"(a[3]), "r"(b0), "r"(b1));
}

// permuted W': kp<512: W[o*17+(kp&15)][ch=kp>>4]; 512+i: bias(i); 528+q: W[o*17+16][q];
//              560: bias(16); else 0
static __device__ __forceinline__ float wval(const float* cw, const float* cb,
                                             int h, int kp, int o) {
    if (kp < 512) { int ch = kp >> 4, i = kp & 15; return cw[(h * 544 + o * 17 + i) * 32 + ch]; }
    if (kp < 528) return cb[h * 544 + o * 17 + (kp - 512)];
    if (kp < 560) return cw[(h * 544 + o * 17 + 16) * 32 + (kp - 528)];
    if (kp == 560) return cb[h * 544 + o * 17 + 16];
    return 0.0f;
}
__global__ void mml_prep_k(const float* __restrict__ cw, const float* __restrict__ cb) {
    int idx = blockIdx.x * blockDim.x + threadIdx.x;
    if (idx >= H * NKS * 2 * 32) return;
    int lane = idx & 31;
    int ntp  = (idx >> 5) & 1;
    int ks   = (idx >> 6) % NKS;
    int h    = (idx >> 6) / NKS;
    int g = lane >> 2, t = lane & 3;
    uint32_t v[4];
#pragma unroll
    for (int p = 0; p < 2; p++) {
        int o = (ntp * 2 + p) * 8 + g;
#pragma unroll
        for (int j = 0; j < 2; j++) {
            int k0 = ks * 16 + 2 * t + 8 * j;
            v[p * 2 + j] = cvt2(wval(cw, cb, h, k0, o), wval(cw, cb, h, k0 + 1, o));
        }
    }
    g_wf4[idx] = make_uint4(v[0], v[1], v[2], v[3]);
}

__global__ void __launch_bounds__(NT, 6)
mml_k(const float* __restrict__ input, const float* __restrict__ cond,
      float* __restrict__ out) {
    extern __shared__ float smf[];
    const int tid = threadIdx.x;
    const int wid = tid >> 5;
    const int lane = tid & 31;
    const int h = blockIdx.y;
    const size_t sbase = (size_t)(h * Bn + blockIdx.x * MT);
    const size_t wrow = sbase + wid * 32;      // this warp's first sample

    float* csw = smf + wid * WBLK;             // [ch*33 + s], s 0..31
    float* xsw = csw + 1056;                   // [i*33 + s]

    // ---- warp-local staging ----
    {
        const float* cg = cond + wrow * 32;
#pragma unroll
        for (int s = 0; s < 32; s++) csw[lane * 33 + s] = cg[s * 32 + lane];
        const float4* xg = reinterpret_cast<const float4*>(input + (wrow + lane) * 16);
#pragma unroll
        for (int q = 0; q < 4; q++) {
            float4 v = xg[q];
            xsw[(q * 4 + 0) * 33 + lane] = v.x;
            xsw[(q * 4 + 1) * 33 + lane] = v.y;
            xsw[(q * 4 + 2) * 33 + lane] = v.z;
            xsw[(q * 4 + 3) * 33 + lane] = v.w;
        }
    }
    __syncwarp();

    // per-lane fixed x: rows {g, g+8, g+16, g+24}, k-cols {2t,2t+1,2t+8,2t+9}
    const int g = lane >> 2, t = lane & 3;
    const int ic[4] = { 2 * t, 2 * t + 1, 2 * t + 8, 2 * t + 9 };
    float xg_[4][4];
#pragma unroll
    for (int r = 0; r < 4; r++)
#pragma unroll
        for (int j = 0; j < 4; j++) xg_[r][j] = xsw[ic[j] * 33 + (r * 8 + g)];

    float d[8][4];
#pragma unroll
    for (int n = 0; n < 8; n++)
#pragma unroll
        for (int e = 0; e < 4; e++) d[n][e] = 0.0f;

    const uint4* wH = g_wf4 + (size_t)h * NKS * 2 * 32 + lane;

    // issue all 16 HMMAs of one kstep from two A fragments
    auto do_mmas = [&](const uint32_t a0[4], const uint32_t a1[4], int ks) {
        uint4 whA = wH[(ks * 2 + 0) * 32];
        uint4 whB = wH[(ks * 2 + 1) * 32];
        mma_f16(d[0], a0, whA.x, whA.y);
        mma_f16(d[1], a0, whA.z, whA.w);
        mma_f16(d[2], a0, whB.x, whB.y);
        mma_f16(d[3], a0, whB.z, whB.w);
        mma_f16(d[4], a1, whA.x, whA.y);
        mma_f16(d[5], a1, whA.z, whA.w);
        mma_f16(d[6], a1, whB.x, whB.y);
        mma_f16(d[7], a1, whB.z, whB.w);
    };

    // ---- ksteps 0..31: P = cond[ch] * x[i], ch = ks ----
#pragma unroll 1
    for (int c = 0; c < 8; c++) {
#pragma unroll
        for (int u = 0; u < 4; u++) {
            const int ks = c * 4 + u;
            float cv0 = csw[ks * 33 + g];
            float cv1 = csw[ks * 33 + g + 8];
            float cv2 = csw[ks * 33 + g + 16];
            float cv3 = csw[ks * 33 + g + 24];
            uint32_t a0[4], a1[4];
            a0[0] = cvt2(cv0 * xg_[0][0], cv0 * xg_[0][1]);
            a0[1] = cvt2(cv1 * xg_[1][0], cv1 * xg_[1][1]);
            a0[2] = cvt2(cv0 * xg_[0][2], cv0 * xg_[0][3]);
            a0[3] = cvt2(cv1 * xg_[1][2], cv1 * xg_[1][3]);
            a1[0] = cvt2(cv2 * xg_[2][0], cv2 * xg_[2][1]);
            a1[1] = cvt2(cv3 * xg_[3][0], cv3 * xg_[3][1]);
            a1[2] = cvt2(cv2 * xg_[2][2], cv2 * xg_[2][3]);
            a1[3] = cvt2(cv3 * xg_[3][2], cv3 * xg_[3][3]);
            do_mmas(a0, a1, ks);
        }
    }
    // ---- kstep 32: P = x[i] (bias rows, cv = 1) ----
    {
        uint32_t a0[4], a1[4];
        a0[0] = cvt2(xg_[0][0], xg_[0][1]); a0[1] = cvt2(xg_[1][0], xg_[1][1]);
        a0[2] = cvt2(xg_[0][2], xg_[0][3]); a0[3] = cvt2(xg_[1][2], xg_[1][3]);
        a1[0] = cvt2(xg_[2][0], xg_[2][1]); a1[1] = cvt2(xg_[3][0], xg_[3][1]);
        a1[2] = cvt2(xg_[2][2], xg_[2][3]); a1[3] = cvt2(xg_[3][2], xg_[3][3]);
        do_mmas(a0, a1, 32);
    }
    // ---- ksteps 33,34: P = cond[qb + kcol] ----
#pragma unroll
    for (int u = 0; u < 2; u++) {
        const int qb = u * 16;
        uint32_t a0[4], a1[4];
        a0[0] = cvt2(csw[(qb + ic[0]) * 33 + g],      csw[(qb + ic[1]) * 33 + g]);
        a0[1] = cvt2(csw[(qb + ic[0]) * 33 + g + 8],  csw[(qb + ic[1]) * 33 + g + 8]);
        a0[2] = cvt2(csw[(qb + ic[2]) * 33 + g],      csw[(qb + ic[3]) * 33 + g]);
        a0[3] = cvt2(csw[(qb + ic[2]) * 33 + g + 8],  csw[(qb + ic[3]) * 33 + g + 8]);
        a1[0] = cvt2(csw[(qb + ic[0]) * 33 + g + 16], csw[(qb + ic[1]) * 33 + g + 16]);
        a1[1] = cvt2(csw[(qb + ic[0]) * 33 + g + 24], csw[(qb + ic[1]) * 33 + g + 24]);
        a1[2] = cvt2(csw[(qb + ic[2]) * 33 + g + 16], csw[(qb + ic[3]) * 33 + g + 16]);
        a1[3] = cvt2(csw[(qb + ic[2]) * 33 + g + 24], csw[(qb + ic[3]) * 33 + g + 24]);
        do_mmas(a0, a1, 33 + u);
    }
    // ---- kstep 35: P[.,560] = 1.0, rest 0 ----
    {
        uint32_t one = (t == 0) ? 0x00003C00u : 0u;
        uint32_t a0[4] = { one, one, 0u, 0u };
        uint32_t a1[4] = { one, one, 0u, 0u };
        do_mmas(a0, a1, 35);
    }

    // ---- epilogue: 8 fragment tiles -> rows m0+{g,g+8,g+16,g+24} ----
    {
        const int m0 = wid * 32;
        const int t4 = lane & 3;
#pragma unroll
        for (int tt = 0; tt < 2; tt++) {
#pragma unroll
            for (int nt = 0; nt < 4; nt++) {
                const float* dd = d[tt * 4 + nt];
                int col = nt * 8 + 2 * t4;
                size_t r0 = sbase + m0 + tt * 16 + g;
                *reinterpret_cast<float2*>(out + r0 * OF + col) = make_float2(dd[0], dd[1]);
                *reinterpret_cast<float2*>(out + (r0 + 8) * OF + col) = make_float2(dd[2], dd[3]);
            }
        }
    }
}

extern "C" void kernel_launch(void* const* d_in, const int* in_sizes, int n_in,
                              void* d_out, int out_size) {
    const float* input = (const float*)d_in[0];
    const float* cond  = (const float*)d_in[1];
    const float* cw    = (const float*)d_in[2];
    const float* cb    = (const float*)d_in[3];
    float* out = (float*)d_out;

    int prep = H * NKS * 2 * 32;   // 18432
    mml_prep_k<<<(prep + 255) / 256, 256>>>(cw, cb);

    cudaFuncSetAttribute(mml_k, cudaFuncAttributeMaxDynamicSharedMemorySize, SM_TOTAL);
    dim3 grid(Bn / MT, H);         // (256, 8)
    mml_k<<<grid, NT, SM_TOTAL>>>(input, cond, out);
}

// round 13
// speedup vs baseline: 6.9084x; 1.1110x over previous
#include <cuda_runtime.h>
#include <cuda_fp16.h>
#include <cstdint>

#define H    8
#define Bn   32768
#define OF   32
#define NKS  36            // ksteps of 16 -> K = 576
#define MT   128           // samples per CTA
#define NT   128           // 4 warps, 32 samples/warp (2 m16 tiles)

// W fragments (single fp16 plane), packed for LDG.128:
// uint4 idx = ((h*NKS+ks)*2+ntp)*32+lane
__device__ uint4 g_wf4[H * NKS * 2 * 32];

// smem per warp: csh[ch*33+s] duplicated half2 (1056 u32) + xsw[i*33+s] fp32 (528 f)
#define WBLK  1584                     // u32 words per warp
#define SM_TOTAL (4 * WBLK * 4)        // 25344 bytes

static __device__ __forceinline__ uint32_t cvt2(float p0, float p1) {
    __half2 hv = __floats2half2_rn(p0, p1);
    return *reinterpret_cast<uint32_t*>(&hv);
}
static __device__ __forceinline__ uint32_t hmul2u(uint32_t a, uint32_t b) {
    __half2 r = __hmul2(*reinterpret_cast<__half2*>(&a), *reinterpret_cast<__half2*>(&b));
    return *reinterpret_cast<uint32_t*>(&r);
}
static __device__ __forceinline__ uint32_t lows2(uint32_t a, uint32_t b) {
    __half2 r = __lows2half2(*reinterpret_cast<__half2*>(&a), *reinterpret_cast<__half2*>(&b));
    return *reinterpret_cast<uint32_t*>(&r);
}
static __device__ __forceinline__ void mma_f16(float d[4], const uint32_t a[4],
                                               uint32_t b0, uint32_t b1) {
    asm volatile(
        "mma.sync.aligned.m16n8k16.row.col.f32.f16.f16.f32 "
        "{%0,%1,%2,%3}, {%4,%5,%6,%7}, {%8,%9}, {%0,%1,%2,%3};"
        : "+f"(d[0]), "+f"(d[1]), "+f"(d[2]), "+f"(d[3])
        : "r"(a[0]), "r"(a[1]), "r"(a[2]), "r"(a[3]), "r"(b0), "r"(b1));
}

// permuted W': kp<512: W[o*17+(kp&15)][ch=kp>>4]; 512+i: bias(i); 528+q: W[o*17+16][q];
//              560: bias(16); else 0
static __device__ __forceinline__ float wval(const float* cw, const float* cb,
                                             int h, int kp, int o) {
    if (kp < 512) { int ch = kp >> 4, i = kp & 15; return cw[(h * 544 + o * 17 + i) * 32 + ch]; }
    if (kp < 528) return cb[h * 544 + o * 17 + (kp - 512)];
    if (kp < 560) return cw[(h * 544 + o * 17 + 16) * 32 + (kp - 528)];
    if (kp == 560) return cb[h * 544 + o * 17 + 16];
    return 0.0f;
}
__global__ void mml_prep_k(const float* __restrict__ cw, const float* __restrict__ cb) {
    int idx = blockIdx.x * blockDim.x + threadIdx.x;
    if (idx >= H * NKS * 2 * 32) return;
    int lane = idx & 31;
    int ntp  = (idx >> 5) & 1;
    int ks   = (idx >> 6) % NKS;
    int h    = (idx >> 6) / NKS;
    int g = lane >> 2, t = lane & 3;
    uint32_t v[4];
#pragma unroll
    for (int p = 0; p < 2; p++) {
        int o = (ntp * 2 + p) * 8 + g;
#pragma unroll
        for (int j = 0; j < 2; j++) {
            int k0 = ks * 16 + 2 * t + 8 * j;
            v[p * 2 + j] = cvt2(wval(cw, cb, h, k0, o), wval(cw, cb, h, k0 + 1, o));
        }
    }
    g_wf4[idx] = make_uint4(v[0], v[1], v[2], v[3]);
}

__global__ void __launch_bounds__(NT, 6)
mml_k(const float* __restrict__ input, const float* __restrict__ cond,
      float* __restrict__ out) {
    extern __shared__ uint32_t smu[];
    const int tid = threadIdx.x;
    const int wid = tid >> 5;
    const int lane = tid & 31;
    const int h = blockIdx.y;
    const size_t sbase = (size_t)(h * Bn + blockIdx.x * MT);
    const size_t wrow = sbase + wid * 32;      // this warp's first sample

    uint32_t* csh = smu + wid * WBLK;          // duplicated half2 (c,c): [ch*33 + s]
    float* xsw = reinterpret_cast<float*>(csh + 1056);   // fp32 x: [i*33 + s]

    // ---- warp-local staging ----
    {
        const float* cg = cond + wrow * 32;
#pragma unroll
        for (int s = 0; s < 32; s++) {
            float v = cg[s * 32 + lane];               // channel = lane
            csh[lane * 33 + s] = cvt2(v, v);
        }
        const float4* xg = reinterpret_cast<const float4*>(input + (wrow + lane) * 16);
#pragma unroll
        for (int q = 0; q < 4; q++) {
            float4 v = xg[q];
            xsw[(q * 4 + 0) * 33 + lane] = v.x;
            xsw[(q * 4 + 1) * 33 + lane] = v.y;
            xsw[(q * 4 + 2) * 33 + lane] = v.z;
            xsw[(q * 4 + 3) * 33 + lane] = v.w;
        }
    }
    __syncwarp();

    // per-lane x as half2 pairs, A-fragment layout:
    // xh[r][0] = (x[2t], x[2t+1]) of row g+8r ; xh[r][1] = (x[2t+8], x[2t+9])
    const int g = lane >> 2, t = lane & 3;
    uint32_t xh[4][2];
#pragma unroll
    for (int r = 0; r < 4; r++) {
        const float* xrow = xsw;  // [i*33 + s]
        int s = r * 8 + g;
        xh[r][0] = cvt2(xrow[(2 * t) * 33 + s],     xrow[(2 * t + 1) * 33 + s]);
        xh[r][1] = cvt2(xrow[(2 * t + 8) * 33 + s], xrow[(2 * t + 9) * 33 + s]);
    }

    float d[8][4];
#pragma unroll
    for (int n = 0; n < 8; n++)
#pragma unroll
        for (int e = 0; e < 4; e++) d[n][e] = 0.0f;

    const uint4* wH = g_wf4 + (size_t)h * NKS * 2 * 32 + lane;

    auto do_mmas = [&](const uint32_t a0[4], const uint32_t a1[4], int ks) {
        uint4 whA = wH[(ks * 2 + 0) * 32];
        uint4 whB = wH[(ks * 2 + 1) * 32];
        mma_f16(d[0], a0, whA.x, whA.y);
        mma_f16(d[1], a0, whA.z, whA.w);
        mma_f16(d[2], a0, whB.x, whB.y);
        mma_f16(d[3], a0, whB.z, whB.w);
        mma_f16(d[4], a1, whA.x, whA.y);
        mma_f16(d[5], a1, whA.z, whA.w);
        mma_f16(d[6], a1, whB.x, whB.y);
        mma_f16(d[7], a1, whB.z, whB.w);
    };

    // ---- ksteps 0..31: P = cond[ch] * x[i] (all-fp16 build: 4 LDS + 8 HMUL2) ----
#pragma unroll 1
    for (int c = 0; c < 8; c++) {
#pragma unroll
        for (int u = 0; u < 4; u++) {
            const int ks = c * 4 + u;
            uint32_t cv0 = csh[ks * 33 + g];
            uint32_t cv1 = csh[ks * 33 + g + 8];
            uint32_t cv2 = csh[ks * 33 + g + 16];
            uint32_t cv3 = csh[ks * 33 + g + 24];
            uint32_t a0[4], a1[4];
            a0[0] = hmul2u(cv0, xh[0][0]);
            a0[1] = hmul2u(cv1, xh[1][0]);
            a0[2] = hmul2u(cv0, xh[0][1]);
            a0[3] = hmul2u(cv1, xh[1][1]);
            a1[0] = hmul2u(cv2, xh[2][0]);
            a1[1] = hmul2u(cv3, xh[3][0]);
            a1[2] = hmul2u(cv2, xh[2][1]);
            a1[3] = hmul2u(cv3, xh[3][1]);
            do_mmas(a0, a1, ks);
        }
    }
    // ---- kstep 32: P = x[i] (bias rows, cv = 1) — fragments are xh directly ----
    {
        uint32_t a0[4] = { xh[0][0], xh[1][0], xh[0][1], xh[1][1] };
        uint32_t a1[4] = { xh[2][0], xh[3][0], xh[2][1], xh[3][1] };
        do_mmas(a0, a1, 32);
    }
    // ---- ksteps 33,34: P = cond[qb + kcol] (pair adjacent channels via lows2) ----
#pragma unroll
    for (int u = 0; u < 2; u++) {
        const int qb = u * 16;
        const int i0 = 2 * t, i1 = 2 * t + 1, i2 = 2 * t + 8, i3 = 2 * t + 9;
        uint32_t a0[4], a1[4];
        a0[0] = lows2(csh[(qb + i0) * 33 + g],      csh[(qb + i1) * 33 + g]);
        a0[1] = lows2(csh[(qb + i0) * 33 + g + 8],  csh[(qb + i1) * 33 + g + 8]);
        a0[2] = lows2(csh[(qb + i2) * 33 + g],      csh[(qb + i3) * 33 + g]);
        a0[3] = lows2(csh[(qb + i2) * 33 + g + 8],  csh[(qb + i3) * 33 + g + 8]);
        a1[0] = lows2(csh[(qb + i0) * 33 + g + 16], csh[(qb + i1) * 33 + g + 16]);
        a1[1] = lows2(csh[(qb + i0) * 33 + g + 24], csh[(qb + i1) * 33 + g + 24]);
        a1[2] = lows2(csh[(qb + i2) * 33 + g + 16], csh[(qb + i3) * 33 + g + 16]);
        a1[3] = lows2(csh[(qb + i2) * 33 + g + 24], csh[(qb + i3) * 33 + g + 24]);
        do_mmas(a0, a1, 33 + u);
    }
    // ---- kstep 35: P[.,560] = 1.0, rest 0 ----
    {
        uint32_t one = (t == 0) ? 0x00003C00u : 0u;
        uint32_t a0[4] = { one, one, 0u, 0u };
        uint32_t a1[4] = { one, one, 0u, 0u };
        do_mmas(a0, a1, 35);
    }

    // ---- epilogue: 8 fragment tiles -> rows m0+{g,g+8,g+16,g+24} ----
    {
        const int m0 = wid * 32;
        const int t4 = lane & 3;
#pragma unroll
        for (int tt = 0; tt < 2; tt++) {
#pragma unroll
            for (int nt = 0; nt < 4; nt++) {
                const float* dd = d[tt * 4 + nt];
                int col = nt * 8 + 2 * t4;
                size_t r0 = sbase + m0 + tt * 16 + g;
                *reinterpret_cast<float2*>(out + r0 * OF + col) = make_float2(dd[0], dd[1]);
                *reinterpret_cast<float2*>(out + (r0 + 8) * OF + col) = make_float2(dd[2], dd[3]);
            }
        }
    }
}

extern "C" void kernel_launch(void* const* d_in, const int* in_sizes, int n_in,
                              void* d_out, int out_size) {
    const float* input = (const float*)d_in[0];
    const float* cond  = (const float*)d_in[1];
    const float* cw    = (const float*)d_in[2];
    const float* cb    = (const float*)d_in[3];
    float* out = (float*)d_out;

    int prep = H * NKS * 2 * 32;   // 18432
    mml_prep_k<<<(prep + 255) / 256, 256>>>(cw, cb);

    cudaFuncSetAttribute(mml_k, cudaFuncAttributeMaxDynamicSharedMemorySize, SM_TOTAL);
    dim3 grid(Bn / MT, H);         // (256, 8)
    mml_k<<<grid, NT, SM_TOTAL>>>(input, cond, out);
}

// round 14
// speedup vs baseline: 7.2283x; 1.0463x over previous
#include <cuda_runtime.h>
#include <cuda_fp16.h>
#include <cstdint>

#define H    8
#define Bn   32768
#define OF   32
#define NKS  36            // ksteps of 16 -> K = 576
#define MT   128           // samples per CTA
#define NT   128           // 4 warps, 32 samples/warp (2 m16 tiles)

// W fragments (single fp16 plane), packed for LDG.128:
// uint4 idx = ((h*NKS+ks)*2+ntp)*32+lane
__device__ uint4 g_wf4[H * NKS * 2 * 32];

// smem per warp: csh[ch*33+s] duplicated half2 (1056 u32) + xsw[i*33+s] fp32 (528 f)
#define WBLK  1584                     // u32 words per warp
#define SM_TOTAL (4 * WBLK * 4)        // 25344 bytes

static __device__ __forceinline__ uint32_t cvt2(float p0, float p1) {
    __half2 hv = __floats2half2_rn(p0, p1);
    return *reinterpret_cast<uint32_t*>(&hv);
}
static __device__ __forceinline__ uint32_t hmul2u(uint32_t a, uint32_t b) {
    __half2 r = __hmul2(*reinterpret_cast<__half2*>(&a), *reinterpret_cast<__half2*>(&b));
    return *reinterpret_cast<uint32_t*>(&r);
}
static __device__ __forceinline__ uint32_t lows2(uint32_t a, uint32_t b) {
    __half2 r = __lows2half2(*reinterpret_cast<__half2*>(&a), *reinterpret_cast<__half2*>(&b));
    return *reinterpret_cast<uint32_t*>(&r);
}
static __device__ __forceinline__ void mma_f16(float d[4], const uint32_t a[4],
                                               uint32_t b0, uint32_t b1) {
    asm volatile(
        "mma.sync.aligned.m16n8k16.row.col.f32.f16.f16.f32 "
        "{%0,%1,%2,%3}, {%4,%5,%6,%7}, {%8,%9}, {%0,%1,%2,%3};"
        : "+f"(d[0]), "+f"(d[1]), "+f"(d[2]), "+f"(d[3])
        : "r"(a[0]), "r"(a[1]), "r"(a[2]), "r"(a[3]), "r"(b0), "r"(b1));
}

// permuted W': kp<512: W[o*17+(kp&15)][ch=kp>>4]; 512+i: bias(i); 528+q: W[o*17+16][q];
//              560: bias(16); else 0
static __device__ __forceinline__ float wval(const float* cw, const float* cb,
                                             int h, int kp, int o) {
    if (kp < 512) { int ch = kp >> 4, i = kp & 15; return cw[(h * 544 + o * 17 + i) * 32 + ch]; }
    if (kp < 528) return cb[h * 544 + o * 17 + (kp - 512)];
    if (kp < 560) return cw[(h * 544 + o * 17 + 16) * 32 + (kp - 528)];
    if (kp == 560) return cb[h * 544 + o * 17 + 16];
    return 0.0f;
}
__global__ void mml_prep_k(const float* __restrict__ cw, const float* __restrict__ cb) {
    int idx = blockIdx.x * blockDim.x + threadIdx.x;
    if (idx >= H * NKS * 2 * 32) return;
    int lane = idx & 31;
    int ntp  = (idx >> 5) & 1;
    int ks   = (idx >> 6) % NKS;
    int h    = (idx >> 6) / NKS;
    int g = lane >> 2, t = lane & 3;
    uint32_t v[4];
#pragma unroll
    for (int p = 0; p < 2; p++) {
        int o = (ntp * 2 + p) * 8 + g;
#pragma unroll
        for (int j = 0; j < 2; j++) {
            int k0 = ks * 16 + 2 * t + 8 * j;
            v[p * 2 + j] = cvt2(wval(cw, cb, h, k0, o), wval(cw, cb, h, k0 + 1, o));
        }
    }
    g_wf4[idx] = make_uint4(v[0], v[1], v[2], v[3]);
}

__global__ void __launch_bounds__(NT, 5)
mml_k(const float* __restrict__ input, const float* __restrict__ cond,
      float* __restrict__ out) {
    extern __shared__ uint32_t smu[];
    const int tid = threadIdx.x;
    const int wid = tid >> 5;
    const int lane = tid & 31;
    const int h = blockIdx.y;
    const size_t sbase = (size_t)(h * Bn + blockIdx.x * MT);
    const size_t wrow = sbase + wid * 32;      // this warp's first sample

    uint32_t* csh = smu + wid * WBLK;          // duplicated half2 (c,c): [ch*33 + s]
    float* xsw = reinterpret_cast<float*>(csh + 1056);   // fp32 x: [i*33 + s]

    // ---- warp-local staging ----
    {
        const float* cg = cond + wrow * 32;
#pragma unroll
        for (int s = 0; s < 32; s++) {
            float v = cg[s * 32 + lane];               // channel = lane
            csh[lane * 33 + s] = cvt2(v, v);
        }
        const float4* xg = reinterpret_cast<const float4*>(input + (wrow + lane) * 16);
#pragma unroll
        for (int q = 0; q < 4; q++) {
            float4 v = xg[q];
            xsw[(q * 4 + 0) * 33 + lane] = v.x;
            xsw[(q * 4 + 1) * 33 + lane] = v.y;
            xsw[(q * 4 + 2) * 33 + lane] = v.z;
            xsw[(q * 4 + 3) * 33 + lane] = v.w;
        }
    }
    __syncwarp();

    // per-lane x as half2 pairs, A-fragment layout
    const int g = lane >> 2, t = lane & 3;
    uint32_t xh[4][2];
#pragma unroll
    for (int r = 0; r < 4; r++) {
        int s = r * 8 + g;
        xh[r][0] = cvt2(xsw[(2 * t) * 33 + s],     xsw[(2 * t + 1) * 33 + s]);
        xh[r][1] = cvt2(xsw[(2 * t + 8) * 33 + s], xsw[(2 * t + 9) * 33 + s]);
    }

    float d[8][4];
#pragma unroll
    for (int n = 0; n < 8; n++)
#pragma unroll
        for (int e = 0; e < 4; e++) d[n][e] = 0.0f;

    const uint4* wH = g_wf4 + (size_t)h * NKS * 2 * 32 + lane;

    auto do_mmas = [&](const uint32_t a0[4], const uint32_t a1[4], uint4 wa, uint4 wb) {
        mma_f16(d[0], a0, wa.x, wa.y);
        mma_f16(d[1], a0, wa.z, wa.w);
        mma_f16(d[2], a0, wb.x, wb.y);
        mma_f16(d[3], a0, wb.z, wb.w);
        mma_f16(d[4], a1, wa.x, wa.y);
        mma_f16(d[5], a1, wa.z, wa.w);
        mma_f16(d[6], a1, wb.x, wb.y);
        mma_f16(d[7], a1, wb.z, wb.w);
    };

    // ---- pipeline state: operands for the CURRENT kstep already in registers ----
    uint32_t cv0 = csh[g], cv1 = csh[g + 8], cv2 = csh[g + 16], cv3 = csh[g + 24];
    uint4 wA = wH[0];
    uint4 wB = wH[32];

    // ---- ksteps 0..31: P = cond[ks] * x[i], 1-deep prefetch of next operands ----
#pragma unroll 1
    for (int c = 0; c < 8; c++) {
#pragma unroll
        for (int u = 0; u < 4; u++) {
            const int ks = c * 4 + u;
            // prefetch kstep ks+1 operands (W uniform; cv only while ks+1 <= 31)
            uint32_t ncv0 = 0, ncv1 = 0, ncv2 = 0, ncv3 = 0;
            if (ks < 31) {
                const uint32_t* cn = csh + (ks + 1) * 33;
                ncv0 = cn[g]; ncv1 = cn[g + 8]; ncv2 = cn[g + 16]; ncv3 = cn[g + 24];
            }
            uint4 nwA = wH[(ks + 1) * 2 * 32];
            uint4 nwB = wH[(ks + 1) * 2 * 32 + 32];
            // build fragments from already-resident operands
            uint32_t a0[4], a1[4];
            a0[0] = hmul2u(cv0, xh[0][0]);
            a0[1] = hmul2u(cv1, xh[1][0]);
            a0[2] = hmul2u(cv0, xh[0][1]);
            a0[3] = hmul2u(cv1, xh[1][1]);
            a1[0] = hmul2u(cv2, xh[2][0]);
            a1[1] = hmul2u(cv3, xh[3][0]);
            a1[2] = hmul2u(cv2, xh[2][1]);
            a1[3] = hmul2u(cv3, xh[3][1]);
            do_mmas(a0, a1, wA, wB);
            cv0 = ncv0; cv1 = ncv1; cv2 = ncv2; cv3 = ncv3;
            wA = nwA; wB = nwB;
        }
    }
    // ---- kstep 32: P = x[i] (cv = 1); W already prefetched in wA/wB ----
    {
        uint32_t a0[4] = { xh[0][0], xh[1][0], xh[0][1], xh[1][1] };
        uint32_t a1[4] = { xh[2][0], xh[3][0], xh[2][1], xh[3][1] };
        do_mmas(a0, a1, wA, wB);
    }
    // ---- ksteps 33,34: P = cond[qb + kcol] ----
#pragma unroll
    for (int u = 0; u < 2; u++) {
        const int ks = 33 + u;
        const int qb = u * 16;
        const int i0 = 2 * t, i1 = 2 * t + 1, i2 = 2 * t + 8, i3 = 2 * t + 9;
        uint4 wa = wH[ks * 2 * 32];
        uint4 wb = wH[ks * 2 * 32 + 32];
        uint32_t a0[4], a1[4];
        a0[0] = lows2(csh[(qb + i0) * 33 + g],      csh[(qb + i1) * 33 + g]);
        a0[1] = lows2(csh[(qb + i0) * 33 + g + 8],  csh[(qb + i1) * 33 + g + 8]);
        a0[2] = lows2(csh[(qb + i2) * 33 + g],      csh[(qb + i3) * 33 + g]);
        a0[3] = lows2(csh[(qb + i2) * 33 + g + 8],  csh[(qb + i3) * 33 + g + 8]);
        a1[0] = lows2(csh[(qb + i0) * 33 + g + 16], csh[(qb + i1) * 33 + g + 16]);
        a1[1] = lows2(csh[(qb + i0) * 33 + g + 24], csh[(qb + i1) * 33 + g + 24]);
        a1[2] = lows2(csh[(qb + i2) * 33 + g + 16], csh[(qb + i3) * 33 + g + 16]);
        a1[3] = lows2(csh[(qb + i2) * 33 + g + 24], csh[(qb + i3) * 33 + g + 24]);
        do_mmas(a0, a1, wa, wb);
    }
    // ---- kstep 35: P[.,560] = 1.0, rest 0 ----
    {
        uint4 wa = wH[35 * 2 * 32];
        uint4 wb = wH[35 * 2 * 32 + 32];
        uint32_t one = (t == 0) ? 0x00003C00u : 0u;
        uint32_t a0[4] = { one, one, 0u, 0u };
        uint32_t a1[4] = { one, one, 0u, 0u };
        do_mmas(a0, a1, wa, wb);
    }

    // ---- epilogue: 8 fragment tiles -> rows m0+{g,g+8,g+16,g+24} ----
    {
        const int m0 = wid * 32;
        const int t4 = lane & 3;
#pragma unroll
        for (int tt = 0; tt < 2; tt++) {
#pragma unroll
            for (int nt = 0; nt < 4; nt++) {
                const float* dd = d[tt * 4 + nt];
                int col = nt * 8 + 2 * t4;
                size_t r0 = sbase + m0 + tt * 16 + g;
                *reinterpret_cast<float2*>(out + r0 * OF + col) = make_float2(dd[0], dd[1]);
                *reinterpret_cast<float2*>(out + (r0 + 8) * OF + col) = make_float2(dd[2], dd[3]);
            }
        }
    }
}

extern "C" void kernel_launch(void* const* d_in, const int* in_sizes, int n_in,
                              void* d_out, int out_size) {
    const float* input = (const float*)d_in[0];
    const float* cond  = (const float*)d_in[1];
    const float* cw    = (const float*)d_in[2];
    const float* cb    = (const float*)d_in[3];
    float* out = (float*)d_out;

    int prep = H * NKS * 2 * 32;   // 18432
    mml_prep_k<<<(prep + 255) / 256, 256>>>(cw, cb);

    cudaFuncSetAttribute(mml_k, cudaFuncAttributeMaxDynamicSharedMemorySize, SM_TOTAL);
    dim3 grid(Bn / MT, H);         // (256, 8)
    mml_k<<<grid, NT, SM_TOTAL>>>(input, cond, out);
}